// round 2
// baseline (speedup 1.0000x reference)
#include <cuda_runtime.h>
#include <cstdint>

#define T_SEQ  512
#define NBATCH 128
#define DIN    256
#define DH     1024
#define NRANK  128
#define DOUT   256

#define NCTA_REC 128u

// ---------------- scratch (static device allocations are the sanctioned path) ----
__device__ float g_zi[(size_t)T_SEQ * NBATCH * DH];            // input projection
__device__ float g_hidden_scratch[(size_t)T_SEQ * NBATCH * DH]; // only if d_out holds output alone
__device__ float g_h[NBATCH * DH];                              // current hidden state
__device__ float g_P[NBATCH * NRANK];                           // rank projection
__device__ unsigned g_bar_count = 0;
__device__ volatile unsigned g_bar_gen = 0;

// ---------------- grid barrier (gen/counter, re-entrant, multi-launch safe) ------
__device__ __forceinline__ void grid_sync()
{
    __threadfence();
    __syncthreads();
    if (threadIdx.x == 0) {
        unsigned gen = g_bar_gen;
        if (atomicAdd(&g_bar_count, 1u) == NCTA_REC - 1u) {
            atomicExch(&g_bar_count, 0u);
            __threadfence();
            g_bar_gen = gen + 1u;
        } else {
            while (g_bar_gen == gen) { __nanosleep(64); }
        }
        __threadfence();
    }
    __syncthreads();
}

// ---------------- persistent recurrence kernel -----------------------------------
// 128 CTAs x 256 threads. CTA c:
//   stage1: b-tile bt = c>>4 (16 rows), r-slice r0 = (c&15)*8  -> P[b_tile, r0..r0+7]
//   stage2: same b-tile,  j-slice j0 = (c&15)*64               -> h'[b_tile, j0..j0+63]
// smem (floats): U_s[8][1028] | h_s[16][1028] | Vt_s[128][68] | P_s[16][128] | red[256]
#define SM_U   0
#define SM_H   8224
#define SM_VT  24672
#define SM_P   33376
#define SM_RED 35424
#define SM_TOTAL_FLOATS 35680
#define SM_TOTAL_BYTES  (SM_TOTAL_FLOATS * 4)

__global__ void __launch_bounds__(256, 1)
rnn_recurrence_kernel(const float* __restrict__ U, const float* __restrict__ V,
                      const float* __restrict__ bh, float* __restrict__ hidden)
{
    extern __shared__ float smem[];
    float* U_s  = smem + SM_U;
    float* h_s  = smem + SM_H;
    float* Vt_s = smem + SM_VT;
    float* P_s  = smem + SM_P;
    float* red  = smem + SM_RED;

    const int cta = blockIdx.x;
    const int tid = threadIdx.x;
    const int b0  = (cta >> 4) * 16;
    const int r0  = (cta & 15) * 8;
    const int j0  = (cta & 15) * 64;

    // load U slice [8][1024] (persistent)
    for (int idx = tid; idx < 8 * 256; idx += 256) {
        int row = idx >> 8, c4 = (idx & 255) << 2;
        *(float4*)(U_s + row * 1028 + c4) =
            *(const float4*)(U + (size_t)(r0 + row) * DH + c4);
    }
    // load V slice transposed: Vt_s[r][jj] = V[(j0+jj)*RANK + r] (persistent)
    for (int idx = tid; idx < 64 * NRANK; idx += 256) {
        int jj = idx >> 7, r = idx & 127;
        Vt_s[r * 68 + jj] = V[(size_t)(j0 + jj) * NRANK + r];
    }
    // stage2 thread mapping + bias preload
    const int b2  = tid >> 4;          // 0..15
    const int jj0 = (tid & 15) << 2;   // 0..60
    const float4 bias4 = *(const float4*)(bh + j0 + jj0);

    // zero h0
    {
        float4 z4 = make_float4(0.f, 0.f, 0.f, 0.f);
        for (int idx = tid; idx < 256; idx += 256)
            ((float4*)g_h)[cta * 256 + idx] = z4;
    }
    // stage1 thread mapping
    const int o = tid & 127, half = tid >> 7;
    const int b1 = o >> 3, r1 = o & 7;
    const float* hrow = h_s + b1 * 1028 + half * 512;
    const float* urow = U_s + r1 * 1028 + half * 512;

    grid_sync();

    for (int t = 0; t < T_SEQ; ++t) {
        // ---- stage h[b_tile, :] into smem
        for (int idx = tid; idx < 16 * 256; idx += 256) {
            int row = idx >> 8, c4 = (idx & 255) << 2;
            *(float4*)(h_s + row * 1028 + c4) =
                *(const float4*)(g_h + (size_t)(b0 + row) * DH + c4);
        }
        __syncthreads();

        // ---- stage1: P[b, r0+r1] partial over half the K range
        float acc = 0.f;
        #pragma unroll 16
        for (int k = 0; k < 512; k += 4) {
            float4 hv = *(const float4*)(hrow + k);
            float4 uv = *(const float4*)(urow + k);
            acc += hv.x * uv.x + hv.y * uv.y + hv.z * uv.z + hv.w * uv.w;
        }
        red[tid] = acc;
        __syncthreads();
        if (tid < 128)
            g_P[(size_t)(b0 + b1) * NRANK + r0 + r1] = red[tid] + red[tid + 128];

        grid_sync();

        // ---- stage P[b_tile, :] into smem
        for (int idx = tid; idx < 16 * 32; idx += 256) {
            int row = idx >> 5, c4 = (idx & 31) << 2;
            *(float4*)(P_s + row * 128 + c4) =
                *(const float4*)(g_P + (size_t)(b0 + row) * NRANK + c4);
        }
        __syncthreads();

        // ---- stage2: h'[b, j0+jj0..+3]
        float4 a4 = bias4;
        const float* pp = P_s + b2 * 128;
        #pragma unroll 8
        for (int r = 0; r < NRANK; r += 4) {
            float4 p4 = *(const float4*)(pp + r);
            const float* vb = Vt_s + r * 68 + jj0;
            float4 v0 = *(const float4*)(vb);
            float4 v1 = *(const float4*)(vb + 68);
            float4 v2 = *(const float4*)(vb + 136);
            float4 v3 = *(const float4*)(vb + 204);
            a4.x += p4.x * v0.x + p4.y * v1.x + p4.z * v2.x + p4.w * v3.x;
            a4.y += p4.x * v0.y + p4.y * v1.y + p4.z * v2.y + p4.w * v3.y;
            a4.z += p4.x * v0.z + p4.y * v1.z + p4.z * v2.z + p4.w * v3.z;
            a4.w += p4.x * v0.w + p4.y * v1.w + p4.z * v2.w + p4.w * v3.w;
        }
        const size_t gz = (size_t)t * (NBATCH * DH) + (size_t)(b0 + b2) * DH + j0 + jj0;
        float4 z = *(const float4*)(g_zi + gz);
        float4 hv;
        hv.x = fmaxf(a4.x + z.x, 0.f);
        hv.y = fmaxf(a4.y + z.y, 0.f);
        hv.z = fmaxf(a4.z + z.z, 0.f);
        hv.w = fmaxf(a4.w + z.w, 0.f);
        *(float4*)(g_h + (size_t)(b0 + b2) * DH + j0 + jj0) = hv;
        *(float4*)(hidden + gz) = hv;

        grid_sync();
    }
}

// ---------------- fp32 NT GEMM: C[m,n] = sum_k A[m,k]*B[n,k] (+bias[n]) ----------
// BM=BN=128, BK=16, 256 threads, 8x8 per-thread microtile.
template <bool BIAS>
__global__ void __launch_bounds__(256, 2)
gemm_nt_kernel(const float* __restrict__ A, const float* __restrict__ B,
               const float* __restrict__ bias, float* __restrict__ C,
               int M, int N, int K)
{
    __shared__ float As[16][132];
    __shared__ float Bs[16][132];

    const int tid = threadIdx.x;
    const int m0 = blockIdx.y * 128;
    const int n0 = blockIdx.x * 128;
    const int lm = tid >> 2;            // 0..63
    const int lk = (tid & 3) << 2;      // 0,4,8,12
    const int row0 = (tid >> 4) * 8;    // 0..120
    const int col0 = (tid & 15) * 8;    // 0..120

    float acc[8][8];
    #pragma unroll
    for (int i = 0; i < 8; ++i)
        #pragma unroll
        for (int j = 0; j < 8; ++j) acc[i][j] = 0.f;

    for (int kt = 0; kt < K; kt += 16) {
        float4 a0 = *(const float4*)(A + (size_t)(m0 + lm) * K + kt + lk);
        float4 a1 = *(const float4*)(A + (size_t)(m0 + lm + 64) * K + kt + lk);
        float4 b0 = *(const float4*)(B + (size_t)(n0 + lm) * K + kt + lk);
        float4 b1 = *(const float4*)(B + (size_t)(n0 + lm + 64) * K + kt + lk);
        __syncthreads();  // previous tile fully consumed
        As[lk + 0][lm] = a0.x; As[lk + 1][lm] = a0.y;
        As[lk + 2][lm] = a0.z; As[lk + 3][lm] = a0.w;
        As[lk + 0][lm + 64] = a1.x; As[lk + 1][lm + 64] = a1.y;
        As[lk + 2][lm + 64] = a1.z; As[lk + 3][lm + 64] = a1.w;
        Bs[lk + 0][lm] = b0.x; Bs[lk + 1][lm] = b0.y;
        Bs[lk + 2][lm] = b0.z; Bs[lk + 3][lm] = b0.w;
        Bs[lk + 0][lm + 64] = b1.x; Bs[lk + 1][lm + 64] = b1.y;
        Bs[lk + 2][lm + 64] = b1.z; Bs[lk + 3][lm + 64] = b1.w;
        __syncthreads();
        #pragma unroll
        for (int k = 0; k < 16; ++k) {
            float a[8], b[8];
            *(float4*)(a)     = *(const float4*)&As[k][row0];
            *(float4*)(a + 4) = *(const float4*)&As[k][row0 + 4];
            *(float4*)(b)     = *(const float4*)&Bs[k][col0];
            *(float4*)(b + 4) = *(const float4*)&Bs[k][col0 + 4];
            #pragma unroll
            for (int i = 0; i < 8; ++i)
                #pragma unroll
                for (int j = 0; j < 8; ++j)
                    acc[i][j] += a[i] * b[j];
        }
    }

    float bias_lo[4] = {0.f, 0.f, 0.f, 0.f}, bias_hi[4] = {0.f, 0.f, 0.f, 0.f};
    if (BIAS) {
        *(float4*)bias_lo = *(const float4*)(bias + n0 + col0);
        *(float4*)bias_hi = *(const float4*)(bias + n0 + col0 + 4);
    }
    #pragma unroll
    for (int i = 0; i < 8; ++i) {
        float* cp = C + (size_t)(m0 + row0 + i) * N + n0 + col0;
        float4 lo, hi;
        lo.x = acc[i][0] + bias_lo[0]; lo.y = acc[i][1] + bias_lo[1];
        lo.z = acc[i][2] + bias_lo[2]; lo.w = acc[i][3] + bias_lo[3];
        hi.x = acc[i][4] + bias_hi[0]; hi.y = acc[i][5] + bias_hi[1];
        hi.z = acc[i][6] + bias_hi[2]; hi.w = acc[i][7] + bias_hi[3];
        *(float4*)(cp)     = lo;
        *(float4*)(cp + 4) = hi;
    }
}

// ---------------- launcher -------------------------------------------------------
extern "C" void kernel_launch(void* const* d_in, const int* in_sizes, int n_in,
                              void* d_out, int out_size)
{
    const float* x     = (const float*)d_in[0];  // [T,B,DIN]
    const float* W_in  = (const float*)d_in[1];  // [DH,DIN]
    const float* U     = (const float*)d_in[2];  // [RANK,DH]
    const float* V     = (const float*)d_in[3];  // [DH,RANK]
    const float* b_h   = (const float*)d_in[4];  // [DH]
    const float* W_out = (const float*)d_in[5];  // [DOUT,DH]
    const float* b_out = (const float*)d_in[6];  // [DOUT]

    float* zi_ptr = nullptr;
    float* hscratch = nullptr;
    cudaGetSymbolAddress((void**)&zi_ptr, g_zi);
    cudaGetSymbolAddress((void**)&hscratch, g_hidden_scratch);

    const size_t HID_ELEMS = (size_t)T_SEQ * NBATCH * DH;   // 67108864
    const size_t OUT_ELEMS = (size_t)T_SEQ * NBATCH * DOUT; // 16777216

    float* hidden_ptr;
    float* out_ptr;
    bool do_output = true;
    if ((size_t)out_size >= HID_ELEMS + OUT_ELEMS) {        // (hidden, output) concat
        hidden_ptr = (float*)d_out;
        out_ptr    = (float*)d_out + HID_ELEMS;
    } else if ((size_t)out_size == HID_ELEMS) {             // hidden only
        hidden_ptr = (float*)d_out;
        out_ptr    = nullptr;
        do_output  = false;
    } else {                                                // output only
        hidden_ptr = hscratch;
        out_ptr    = (float*)d_out;
    }

    cudaFuncSetAttribute(rnn_recurrence_kernel,
                         cudaFuncAttributeMaxDynamicSharedMemorySize, SM_TOTAL_BYTES);

    const int M = T_SEQ * NBATCH;  // 65536

    // phase 1: zi = x @ W_in^T
    {
        dim3 grid(DH / 128, M / 128);
        gemm_nt_kernel<false><<<grid, 256>>>(x, W_in, nullptr, zi_ptr, M, DH, DIN);
    }
    // phase 2: recurrence (persistent, writes hidden)
    rnn_recurrence_kernel<<<NCTA_REC, 256, SM_TOTAL_BYTES>>>(U, V, b_h, hidden_ptr);

    // phase 3: output = hidden @ W_out^T + b_out
    if (do_output) {
        dim3 grid(DOUT / 128, M / 128);
        gemm_nt_kernel<true><<<grid, 256>>>(hidden_ptr, W_out, b_out, out_ptr, M, DOUT, DH);
    }
}

// round 3
// speedup vs baseline: 1.3430x; 1.3430x over previous
#include <cuda_runtime.h>
#include <cstdint>

#define T_SEQ  512
#define NBATCH 128
#define DIN    256
#define DH     1024
#define NRANK  128
#define DOUT   256

// ---------------- scratch ---------------------------------------------------------
__device__ float g_zi[(size_t)T_SEQ * NBATCH * DH];             // input projection
__device__ float g_hidden_scratch[(size_t)T_SEQ * NBATCH * DH]; // if d_out holds output only
__device__ float g_h[NBATCH * DH];                              // current hidden state
__device__ float g_P[NBATCH * NRANK];                           // rank projection

// ---------------- cluster sync ----------------------------------------------------
__device__ __forceinline__ void cluster_sync()
{
    asm volatile("barrier.cluster.arrive.aligned;" ::: "memory");
    asm volatile("barrier.cluster.wait.aligned;" ::: "memory");
}

// ---------------- persistent recurrence kernel ------------------------------------
// 16 independent clusters x 8 CTAs. Cluster g owns batches [g*8, g*8+8).
// CTA rank c in cluster:
//   stage1: computes P[8b x 16r] for r-slice r0 = c*16       (K=1024, K-split 32)
//   stage2: computes h'[8b x 128j] for j-slice j0 = c*128    (r=128, r-split 4)
// Communication (P, h) flows through L2 (__ldcg / plain st), ordered by cluster barriers.
//
// smem layout (floats):
#define SM_H    0                 // h_sT[1024][12]   (k-major, 8 b cols + pad)
#define SM_U    12288             // U_sT[1024][20]   (k-major, 16 r cols + pad)
#define SM_VT   32768             // Vt  [128][132]   (r-major, 128 j cols + pad)
#define SM_PT   49664             // P_sT[128][12]    (r-major, 8 b cols + pad)
#define SM_RED  51200             // red [4096]
#define SM_TOTAL_FLOATS 55296
#define SM_TOTAL_BYTES  (SM_TOTAL_FLOATS * 4)

__global__ void __cluster_dims__(8, 1, 1) __launch_bounds__(256, 1)
rnn_recurrence_kernel(const float* __restrict__ U, const float* __restrict__ V,
                      const float* __restrict__ bh, const float* __restrict__ zi,
                      float* __restrict__ hidden)
{
    extern __shared__ float smem[];
    float* h_sT = smem + SM_H;
    float* U_sT = smem + SM_U;
    float* Vt   = smem + SM_VT;
    float* P_sT = smem + SM_PT;
    float* red  = smem + SM_RED;

    const int tid = threadIdx.x;
    const int c   = blockIdx.x & 7;        // cluster rank
    const int g   = blockIdx.x >> 3;       // cluster id
    const int b0g = g * 8;                 // batch base
    const int r0g = c * 16;                // stage1 r-slice
    const int j0g = c * 128;               // stage2 j-slice

    // ---- one-time: stage U slice transposed: U_sT[k][rl] = U[r0g+rl][k]
    #pragma unroll
    for (int i = 0; i < 16; ++i) {
        float4 u4 = *((const float4*)(U + (size_t)(r0g + i) * DH) + tid);
        int kb = tid * 4;
        U_sT[(kb + 0) * 20 + i] = u4.x;
        U_sT[(kb + 1) * 20 + i] = u4.y;
        U_sT[(kb + 2) * 20 + i] = u4.z;
        U_sT[(kb + 3) * 20 + i] = u4.w;
    }
    // ---- one-time: stage V slice transposed: Vt[r][jj] = V[j0g+jj][r]
    #pragma unroll
    for (int it = 0; it < 16; ++it) {
        int flat = it * 256 + tid;
        int jj = flat >> 5;
        int r4 = (flat & 31) << 2;
        float4 v4 = *(const float4*)(V + (size_t)(j0g + jj) * NRANK + r4);
        Vt[(r4 + 0) * 132 + jj] = v4.x;
        Vt[(r4 + 1) * 132 + jj] = v4.y;
        Vt[(r4 + 2) * 132 + jj] = v4.z;
        Vt[(r4 + 3) * 132 + jj] = v4.w;
    }

    // ---- per-thread fixed mappings
    // stage1: kq in 0..31, tile = (bt:2) x (rt:4)
    const int kq   = tid >> 3;
    const int b0s1 = (tid & 1) * 4;        // bt
    const int r0s1 = ((tid >> 1) & 3) * 4; // rt
    // stage2: rq in 0..3, tile = (bt:2) x (jt:32)
    const int rq   = tid & 3;
    const int b0s2 = ((tid >> 2) & 1) * 4;
    const int j2   = (tid >> 3) * 4;       // 0..124
    // stage2 epilogue: output quad o4 = tid*4 -> (b, jj)
    const int eb   = tid >> 5;             // 0..7
    const int ejj  = (tid & 31) << 2;      // 0..124
    const float4 bias4 = *(const float4*)(bh + j0g + ejj);

    // ---- zero this CTA's h region (its stage2 output rows/cols)
    {
        float4 z4 = make_float4(0.f, 0.f, 0.f, 0.f);
        *(float4*)(g_h + (size_t)(b0g + eb) * DH + j0g + ejj) = z4;
    }
    __syncthreads();
    cluster_sync();

    for (int t = 0; t < T_SEQ; ++t) {
        // prefetch zi for this thread's stage2 outputs (consumed ~2000 cyc later)
        const size_t gz = (size_t)t * (NBATCH * DH) + (size_t)(b0g + eb) * DH + j0g + ejj;
        const float4 zi4 = __ldg((const float4*)(zi + gz));

        // ---- stage h tile transposed into smem: h_sT[k][b] (8 b cols)
        #pragma unroll
        for (int i = 0; i < 8; ++i) {
            float4 h4 = __ldcg((const float4*)(g_h + (size_t)(b0g + i) * DH) + tid);
            int kb = tid * 4;
            h_sT[(kb + 0) * 12 + i] = h4.x;
            h_sT[(kb + 1) * 12 + i] = h4.y;
            h_sT[(kb + 2) * 12 + i] = h4.z;
            h_sT[(kb + 3) * 12 + i] = h4.w;
        }
        __syncthreads();

        // ---- stage1: acc[4b][4r] over k = kq + 32*i
        float a1[4][4];
        #pragma unroll
        for (int x = 0; x < 4; ++x)
            #pragma unroll
            for (int y = 0; y < 4; ++y) a1[x][y] = 0.f;
        #pragma unroll 8
        for (int i = 0; i < 32; ++i) {
            int k = kq + (i << 5);
            float4 h4 = *(const float4*)(h_sT + k * 12 + b0s1);
            float4 u4 = *(const float4*)(U_sT + k * 20 + r0s1);
            a1[0][0] += h4.x * u4.x; a1[0][1] += h4.x * u4.y; a1[0][2] += h4.x * u4.z; a1[0][3] += h4.x * u4.w;
            a1[1][0] += h4.y * u4.x; a1[1][1] += h4.y * u4.y; a1[1][2] += h4.y * u4.z; a1[1][3] += h4.y * u4.w;
            a1[2][0] += h4.z * u4.x; a1[2][1] += h4.z * u4.y; a1[2][2] += h4.z * u4.z; a1[2][3] += h4.z * u4.w;
            a1[3][0] += h4.w * u4.x; a1[3][1] += h4.w * u4.y; a1[3][2] += h4.w * u4.z; a1[3][3] += h4.w * u4.w;
        }
        // reduce 32 k-slices: red[kq][o], o = b*16 + r (128 outputs)
        #pragma unroll
        for (int bi = 0; bi < 4; ++bi)
            #pragma unroll
            for (int ri = 0; ri < 4; ++ri)
                red[kq * 128 + (b0s1 + bi) * 16 + (r0s1 + ri)] = a1[bi][ri];
        __syncthreads();
        if (tid < 128) {
            float s = 0.f;
            #pragma unroll 8
            for (int q = 0; q < 32; ++q) s += red[q * 128 + tid];
            g_P[(size_t)(b0g + (tid >> 4)) * NRANK + r0g + (tid & 15)] = s;
        }
        cluster_sync();   // P visible cluster-wide

        // ---- stage P tile transposed: P_sT[r][b]
        {
            int b  = tid >> 5;
            int r4 = (tid & 31) << 2;
            float4 p4 = __ldcg((const float4*)(g_P + (size_t)(b0g + b) * NRANK + r4));
            P_sT[(r4 + 0) * 12 + b] = p4.x;
            P_sT[(r4 + 1) * 12 + b] = p4.y;
            P_sT[(r4 + 2) * 12 + b] = p4.z;
            P_sT[(r4 + 3) * 12 + b] = p4.w;
        }
        __syncthreads();

        // ---- stage2: acc[4b][4j] over r = rq + 4*i
        float a2[4][4];
        #pragma unroll
        for (int x = 0; x < 4; ++x)
            #pragma unroll
            for (int y = 0; y < 4; ++y) a2[x][y] = 0.f;
        #pragma unroll 8
        for (int i = 0; i < 32; ++i) {
            int r = rq + (i << 2);
            float4 p4 = *(const float4*)(P_sT + r * 12 + b0s2);
            float4 v4 = *(const float4*)(Vt + r * 132 + j2);
            a2[0][0] += p4.x * v4.x; a2[0][1] += p4.x * v4.y; a2[0][2] += p4.x * v4.z; a2[0][3] += p4.x * v4.w;
            a2[1][0] += p4.y * v4.x; a2[1][1] += p4.y * v4.y; a2[1][2] += p4.y * v4.z; a2[1][3] += p4.y * v4.w;
            a2[2][0] += p4.z * v4.x; a2[2][1] += p4.z * v4.y; a2[2][2] += p4.z * v4.z; a2[2][3] += p4.z * v4.w;
            a2[3][0] += p4.w * v4.x; a2[3][1] += p4.w * v4.y; a2[3][2] += p4.w * v4.z; a2[3][3] += p4.w * v4.w;
        }
        // reduce 4 r-slices: red[rq][o], o = b*128 + j (1024 outputs)
        #pragma unroll
        for (int bi = 0; bi < 4; ++bi)
            #pragma unroll
            for (int ji = 0; ji < 4; ++ji)
                red[rq * 1024 + (b0s2 + bi) * 128 + (j2 + ji)] = a2[bi][ji];
        __syncthreads();
        {
            int o4 = tid << 2;
            float4 s0 = *(const float4*)(red + o4);
            float4 s1 = *(const float4*)(red + 1024 + o4);
            float4 s2 = *(const float4*)(red + 2048 + o4);
            float4 s3 = *(const float4*)(red + 3072 + o4);
            float4 hv;
            hv.x = fmaxf(s0.x + s1.x + s2.x + s3.x + bias4.x + zi4.x, 0.f);
            hv.y = fmaxf(s0.y + s1.y + s2.y + s3.y + bias4.y + zi4.y, 0.f);
            hv.z = fmaxf(s0.z + s1.z + s2.z + s3.z + bias4.z + zi4.z, 0.f);
            hv.w = fmaxf(s0.w + s1.w + s2.w + s3.w + bias4.w + zi4.w, 0.f);
            *(float4*)(g_h + (size_t)(b0g + eb) * DH + j0g + ejj) = hv;
            *(float4*)(hidden + gz) = hv;
        }
        cluster_sync();   // h visible cluster-wide before next staging
    }
}

// ---------------- fp32 NT GEMM, smem double-buffered ------------------------------
// C[m,n] = sum_k A[m,k]*B[n,k] (+bias[n]); BM=BN=128, BK=16, 256 thr, 8x8 microtile.
template <bool BIAS>
__global__ void __launch_bounds__(256, 2)
gemm_nt_kernel(const float* __restrict__ A, const float* __restrict__ B,
               const float* __restrict__ bias, float* __restrict__ C,
               int M, int N, int K)
{
    __shared__ float As[2][16][132];
    __shared__ float Bs[2][16][132];

    const int tid = threadIdx.x;
    const int m0 = blockIdx.y * 128;
    const int n0 = blockIdx.x * 128;
    const int lm = tid >> 2;            // 0..63
    const int lk = (tid & 3) << 2;      // 0,4,8,12
    const int row0 = (tid >> 4) * 8;
    const int col0 = (tid & 15) * 8;

    const float* Ap0 = A + (size_t)(m0 + lm) * K + lk;
    const float* Ap1 = A + (size_t)(m0 + lm + 64) * K + lk;
    const float* Bp0 = B + (size_t)(n0 + lm) * K + lk;
    const float* Bp1 = B + (size_t)(n0 + lm + 64) * K + lk;

    float acc[8][8];
    #pragma unroll
    for (int i = 0; i < 8; ++i)
        #pragma unroll
        for (int j = 0; j < 8; ++j) acc[i][j] = 0.f;

    // prologue: tile 0 into buffer 0
    {
        float4 a0 = *(const float4*)(Ap0);
        float4 a1 = *(const float4*)(Ap1);
        float4 b0 = *(const float4*)(Bp0);
        float4 b1 = *(const float4*)(Bp1);
        As[0][lk + 0][lm] = a0.x; As[0][lk + 1][lm] = a0.y;
        As[0][lk + 2][lm] = a0.z; As[0][lk + 3][lm] = a0.w;
        As[0][lk + 0][lm + 64] = a1.x; As[0][lk + 1][lm + 64] = a1.y;
        As[0][lk + 2][lm + 64] = a1.z; As[0][lk + 3][lm + 64] = a1.w;
        Bs[0][lk + 0][lm] = b0.x; Bs[0][lk + 1][lm] = b0.y;
        Bs[0][lk + 2][lm] = b0.z; Bs[0][lk + 3][lm] = b0.w;
        Bs[0][lk + 0][lm + 64] = b1.x; Bs[0][lk + 1][lm + 64] = b1.y;
        Bs[0][lk + 2][lm + 64] = b1.z; Bs[0][lk + 3][lm + 64] = b1.w;
    }
    __syncthreads();

    int p = 0;
    for (int kt = 0; kt < K; kt += 16) {
        const bool more = (kt + 16) < K;
        float4 a0, a1, b0, b1;
        if (more) {
            a0 = *(const float4*)(Ap0 + kt + 16);
            a1 = *(const float4*)(Ap1 + kt + 16);
            b0 = *(const float4*)(Bp0 + kt + 16);
            b1 = *(const float4*)(Bp1 + kt + 16);
        }
        #pragma unroll
        for (int k = 0; k < 16; ++k) {
            float a[8], b[8];
            *(float4*)(a)     = *(const float4*)&As[p][k][row0];
            *(float4*)(a + 4) = *(const float4*)&As[p][k][row0 + 4];
            *(float4*)(b)     = *(const float4*)&Bs[p][k][col0];
            *(float4*)(b + 4) = *(const float4*)&Bs[p][k][col0 + 4];
            #pragma unroll
            for (int i = 0; i < 8; ++i)
                #pragma unroll
                for (int j = 0; j < 8; ++j)
                    acc[i][j] += a[i] * b[j];
        }
        if (more) {
            const int q = p ^ 1;
            As[q][lk + 0][lm] = a0.x; As[q][lk + 1][lm] = a0.y;
            As[q][lk + 2][lm] = a0.z; As[q][lk + 3][lm] = a0.w;
            As[q][lk + 0][lm + 64] = a1.x; As[q][lk + 1][lm + 64] = a1.y;
            As[q][lk + 2][lm + 64] = a1.z; As[q][lk + 3][lm + 64] = a1.w;
            Bs[q][lk + 0][lm] = b0.x; Bs[q][lk + 1][lm] = b0.y;
            Bs[q][lk + 2][lm] = b0.z; Bs[q][lk + 3][lm] = b0.w;
            Bs[q][lk + 0][lm + 64] = b1.x; Bs[q][lk + 1][lm + 64] = b1.y;
            Bs[q][lk + 2][lm + 64] = b1.z; Bs[q][lk + 3][lm + 64] = b1.w;
            __syncthreads();
            p = q;
        }
    }

    float bias_lo[4] = {0.f, 0.f, 0.f, 0.f}, bias_hi[4] = {0.f, 0.f, 0.f, 0.f};
    if (BIAS) {
        *(float4*)bias_lo = *(const float4*)(bias + n0 + col0);
        *(float4*)bias_hi = *(const float4*)(bias + n0 + col0 + 4);
    }
    #pragma unroll
    for (int i = 0; i < 8; ++i) {
        float* cp = C + (size_t)(m0 + row0 + i) * N + n0 + col0;
        float4 lo, hi;
        lo.x = acc[i][0] + bias_lo[0]; lo.y = acc[i][1] + bias_lo[1];
        lo.z = acc[i][2] + bias_lo[2]; lo.w = acc[i][3] + bias_lo[3];
        hi.x = acc[i][4] + bias_hi[0]; hi.y = acc[i][5] + bias_hi[1];
        hi.z = acc[i][6] + bias_hi[2]; hi.w = acc[i][7] + bias_hi[3];
        *(float4*)(cp)     = lo;
        *(float4*)(cp + 4) = hi;
    }
}

// ---------------- launcher --------------------------------------------------------
extern "C" void kernel_launch(void* const* d_in, const int* in_sizes, int n_in,
                              void* d_out, int out_size)
{
    const float* x     = (const float*)d_in[0];  // [T,B,DIN]
    const float* W_in  = (const float*)d_in[1];  // [DH,DIN]
    const float* U     = (const float*)d_in[2];  // [RANK,DH]
    const float* V     = (const float*)d_in[3];  // [DH,RANK]
    const float* b_h   = (const float*)d_in[4];  // [DH]
    const float* W_out = (const float*)d_in[5];  // [DOUT,DH]
    const float* b_out = (const float*)d_in[6];  // [DOUT]

    float* zi_ptr = nullptr;
    float* hscratch = nullptr;
    cudaGetSymbolAddress((void**)&zi_ptr, g_zi);
    cudaGetSymbolAddress((void**)&hscratch, g_hidden_scratch);

    const size_t HID_ELEMS = (size_t)T_SEQ * NBATCH * DH;   // 67108864
    const size_t OUT_ELEMS = (size_t)T_SEQ * NBATCH * DOUT; // 16777216

    float* hidden_ptr;
    float* out_ptr;
    bool do_output = true;
    if ((size_t)out_size >= HID_ELEMS + OUT_ELEMS) {        // (hidden, output) concat
        hidden_ptr = (float*)d_out;
        out_ptr    = (float*)d_out + HID_ELEMS;
    } else if ((size_t)out_size == HID_ELEMS) {             // hidden only
        hidden_ptr = (float*)d_out;
        out_ptr    = nullptr;
        do_output  = false;
    } else {                                                // output only
        hidden_ptr = hscratch;
        out_ptr    = (float*)d_out;
    }

    cudaFuncSetAttribute(rnn_recurrence_kernel,
                         cudaFuncAttributeMaxDynamicSharedMemorySize, SM_TOTAL_BYTES);

    const int M = T_SEQ * NBATCH;  // 65536

    // phase 1: zi = x @ W_in^T
    {
        dim3 grid(DH / 128, M / 128);
        gemm_nt_kernel<false><<<grid, 256>>>(x, W_in, nullptr, zi_ptr, M, DH, DIN);
    }
    // phase 2: recurrence (16 independent 8-CTA clusters)
    rnn_recurrence_kernel<<<128, 256, SM_TOTAL_BYTES>>>(U, V, b_h, zi_ptr, hidden_ptr);

    // phase 3: output = hidden @ W_out^T + b_out
    if (do_output) {
        dim3 grid(DOUT / 128, M / 128);
        gemm_nt_kernel<true><<<grid, 256>>>(hidden_ptr, W_out, b_out, out_ptr, M, DOUT, DH);
    }
}

// round 4
// speedup vs baseline: 2.8543x; 2.1253x over previous
#include <cuda_runtime.h>
#include <cstdint>

#define T_SEQ  512
#define NBATCH 128
#define DIN    256
#define DH     1024
#define NRANK  128
#define DOUT   256
#define BDH    (NBATCH * DH)

// ---------------- scratch ---------------------------------------------------------
__device__ float g_zi[(size_t)T_SEQ * NBATCH * DH];
__device__ float g_hidden_scratch[(size_t)T_SEQ * NBATCH * DH];
__device__ float g_P[NBATCH * NRANK];

// ---------------- helpers ---------------------------------------------------------
__device__ __forceinline__ unsigned f2tf(float x)
{
    unsigned r;
    asm("cvt.rna.tf32.f32 %0, %1;" : "=r"(r) : "f"(x));
    return r;
}

__device__ __forceinline__ void mma_tf32(float c[4],
                                         unsigned a0, unsigned a1, unsigned a2, unsigned a3,
                                         unsigned b0, unsigned b1)
{
    asm volatile(
        "mma.sync.aligned.m16n8k8.row.col.f32.tf32.tf32.f32 "
        "{%0,%1,%2,%3}, {%4,%5,%6,%7}, {%8,%9}, {%0,%1,%2,%3};"
        : "+f"(c[0]), "+f"(c[1]), "+f"(c[2]), "+f"(c[3])
        : "r"(a0), "r"(a1), "r"(a2), "r"(a3), "r"(b0), "r"(b1));
}

__device__ __forceinline__ void cluster_sync()
{
    asm volatile("barrier.cluster.arrive.aligned;" ::: "memory");
    asm volatile("barrier.cluster.wait.aligned;" ::: "memory");
}

// ---------------- persistent recurrence kernel (tf32 tensor cores) ----------------
// 16 independent clusters x 8 CTAs; cluster g owns batches [8g, 8g+8).
// CTA rank c: stage1 computes P^T[16r x 8b] for r in [16c,16c+16) (warps split K=1024);
//             stage2 computes h'^T[128j x 8b] for j in [128c,128c+128) (warp w: 16 j rows).
// U/V fragments preloaded into registers once (loop-invariant).
__global__ void __cluster_dims__(8, 1, 1) __launch_bounds__(256, 1)
rnn_rec_tf32(const float* __restrict__ U, const float* __restrict__ V,
             const float* __restrict__ bh, const float* __restrict__ zi,
             float* __restrict__ hidden)
{
    __shared__ unsigned h_s[8][1028];   // [batch][k]  (banks: 4b+k -> conflict-free frags)
    __shared__ unsigned P_s[8][132];    // [batch][r]
    __shared__ float    red[8][132];    // stage1 cross-warp partials

    const int tid  = threadIdx.x;
    const int wid  = tid >> 5;
    const int lane = tid & 31;
    const int grp  = lane >> 2;   // 0..7
    const int qid  = lane & 3;    // 0..3

    const int c   = blockIdx.x & 7;
    const int g   = blockIdx.x >> 3;
    const int b0g = g * 8;
    const int rc  = c * 16;             // stage1 r base
    const int jb  = c * 128 + wid * 16; // stage2 j base for this warp

    // ---- preload U fragments (stage1 A): warp wid covers k in [128*wid, 128*wid+128)
    unsigned ua[16][4];
    #pragma unroll
    for (int i = 0; i < 16; ++i) {
        const int k = wid * 128 + i * 8 + qid;
        ua[i][0] = f2tf(__ldg(U + (size_t)(rc + grp)     * DH + k));
        ua[i][1] = f2tf(__ldg(U + (size_t)(rc + grp + 8) * DH + k));
        ua[i][2] = f2tf(__ldg(U + (size_t)(rc + grp)     * DH + k + 4));
        ua[i][3] = f2tf(__ldg(U + (size_t)(rc + grp + 8) * DH + k + 4));
    }
    // ---- preload V fragments (stage2 A): rows j = jb+grp(+8), k = r
    unsigned va[16][4];
    #pragma unroll
    for (int i = 0; i < 16; ++i) {
        const int r = i * 8 + qid;
        va[i][0] = f2tf(__ldg(V + (size_t)(jb + grp)     * NRANK + r));
        va[i][1] = f2tf(__ldg(V + (size_t)(jb + grp + 8) * NRANK + r));
        va[i][2] = f2tf(__ldg(V + (size_t)(jb + grp)     * NRANK + r + 4));
        va[i][3] = f2tf(__ldg(V + (size_t)(jb + grp + 8) * NRANK + r + 4));
    }
    const float bias0 = __ldg(bh + jb + grp);
    const float bias1 = __ldg(bh + jb + grp + 8);

    // epilogue / zi offsets: element (j,b) at (b)*DH + j
    const size_t o00 = (size_t)(b0g + 2 * qid) * DH + jb + grp;  // (j, b)
    // o00+DH: (j,b+1)   o00+8: (j+8,b)   o00+DH+8: (j+8,b+1)

    // staging maps
    const int sb = tid >> 5;          // batch row (== wid)
    const int sk = (tid & 31) * 4;    // k chunk
    const int pb = tid >> 5;          // P batch row
    const int pr = (tid & 31) * 4;    // P r chunk

    for (int t = 0; t < T_SEQ; ++t) {
        // ---- zi prefetch (consumed in epilogue)
        const float* zit = zi + (size_t)t * BDH;
        const float z00 = __ldg(zit + o00);
        const float z01 = __ldg(zit + o00 + DH);
        const float z10 = __ldg(zit + o00 + 8);
        const float z11 = __ldg(zit + o00 + DH + 8);

        // ---- stage h(t-1) into h_s (tf32), batch-row contiguous
        const float* hp = hidden + (size_t)(t - 1) * BDH + (size_t)(b0g + sb) * DH;
        #pragma unroll
        for (int i = 0; i < 8; ++i) {
            float4 h4 = make_float4(0.f, 0.f, 0.f, 0.f);
            if (t > 0) h4 = __ldcg((const float4*)(hp + sk + i * 128));
            unsigned* d = &h_s[sb][sk + i * 128];
            d[0] = f2tf(h4.x); d[1] = f2tf(h4.y);
            d[2] = f2tf(h4.z); d[3] = f2tf(h4.w);
        }
        __syncthreads();

        // ---- stage1: C1 = U_slice (16x128k) x h^T(128k x 8b), warp-local K slice
        float c1[4] = {0.f, 0.f, 0.f, 0.f};
        #pragma unroll
        for (int i = 0; i < 16; ++i) {
            const int kk = wid * 128 + i * 8;
            const unsigned b0 = h_s[grp][kk + qid];
            const unsigned b1 = h_s[grp][kk + qid + 4];
            mma_tf32(c1, ua[i][0], ua[i][1], ua[i][2], ua[i][3], b0, b1);
        }
        // partials: idx = r_loc*8 + b
        red[wid][grp * 8 + 2 * qid]           = c1[0];
        red[wid][grp * 8 + 2 * qid + 1]       = c1[1];
        red[wid][(grp + 8) * 8 + 2 * qid]     = c1[2];
        red[wid][(grp + 8) * 8 + 2 * qid + 1] = c1[3];
        __syncthreads();
        if (tid < 128) {
            float s = red[0][tid] + red[1][tid] + red[2][tid] + red[3][tid]
                    + red[4][tid] + red[5][tid] + red[6][tid] + red[7][tid];
            const int rl = tid >> 3, bb = tid & 7;
            g_P[(size_t)(b0g + bb) * NRANK + rc + rl] = s;
        }
        cluster_sync();  // P visible cluster-wide

        // ---- stage P into P_s (tf32)
        {
            const float4 p4 = __ldcg((const float4*)(g_P + (size_t)(b0g + pb) * NRANK + pr));
            unsigned* d = &P_s[pb][pr];
            d[0] = f2tf(p4.x); d[1] = f2tf(p4.y);
            d[2] = f2tf(p4.z); d[3] = f2tf(p4.w);
        }
        __syncthreads();

        // ---- stage2: C2 = V_slice (16j x 128r) x P^T(128r x 8b)
        float c2[4] = {0.f, 0.f, 0.f, 0.f};
        #pragma unroll
        for (int i = 0; i < 16; ++i) {
            const unsigned b0 = P_s[grp][i * 8 + qid];
            const unsigned b1 = P_s[grp][i * 8 + qid + 4];
            mma_tf32(c2, va[i][0], va[i][1], va[i][2], va[i][3], b0, b1);
        }
        // ---- epilogue: + bias + zi, relu, store hidden[t]
        float* ht = hidden + (size_t)t * BDH;
        ht[o00]          = fmaxf(c2[0] + bias0 + z00, 0.f);
        ht[o00 + DH]     = fmaxf(c2[1] + bias0 + z01, 0.f);
        ht[o00 + 8]      = fmaxf(c2[2] + bias1 + z10, 0.f);
        ht[o00 + DH + 8] = fmaxf(c2[3] + bias1 + z11, 0.f);
        cluster_sync();  // h(t) visible cluster-wide
    }
}

// ---------------- tf32 NT GEMM: C[m,n] = sum_k A[m,k]*B[n,k] (+bias[n]) -----------
// BM=BN=128, BK=16, 256 threads, warp grid 4m x 2n, warp tile 32x64, m16n8k8.
template <bool BIAS>
__global__ void __launch_bounds__(256, 2)
gemm_tf32_nt(const float* __restrict__ A, const float* __restrict__ B,
             const float* __restrict__ bias, float* __restrict__ C,
             int M, int N, int K)
{
    __shared__ unsigned As[2][16][136];   // [k][m], stride 136 -> conflict-free frags
    __shared__ unsigned Bs[2][16][136];   // [k][n]

    const int tid  = threadIdx.x;
    const int wid  = tid >> 5;
    const int lane = tid & 31;
    const int grp  = lane >> 2;
    const int qid  = lane & 3;
    const int wm   = (wid >> 1) * 32;
    const int wn   = (wid & 1) * 64;
    const int m0   = blockIdx.y * 128;
    const int n0   = blockIdx.x * 128;
    const int lm   = tid >> 2;           // 0..63
    const int lk   = (tid & 3) << 2;     // 0,4,8,12
    const int lk4  = tid & 3;

    const float* Ap0 = A + (size_t)(m0 + lm) * K + lk;
    const float* Ap1 = Ap0 + (size_t)64 * K;
    const float* Bp0 = B + (size_t)(n0 + lm) * K + lk;
    const float* Bp1 = Bp0 + (size_t)64 * K;

    float acc[2][8][4];
    #pragma unroll
    for (int mt = 0; mt < 2; ++mt)
        #pragma unroll
        for (int nt = 0; nt < 8; ++nt)
            #pragma unroll
            for (int j = 0; j < 4; ++j) acc[mt][nt][j] = 0.f;

    // stagger store rows by lane's lk group to dodge bank conflicts
    auto stage = [&](int buf, const float4& a0, const float4& a1,
                     const float4& b0, const float4& b1) {
        float av0[4] = {a0.x, a0.y, a0.z, a0.w};
        float av1[4] = {a1.x, a1.y, a1.z, a1.w};
        float bv0[4] = {b0.x, b0.y, b0.z, b0.w};
        float bv1[4] = {b1.x, b1.y, b1.z, b1.w};
        #pragma unroll
        for (int i = 0; i < 4; ++i) {
            const int ii = (i + lk4) & 3;
            As[buf][lk + ii][lm]      = f2tf(av0[ii]);
            As[buf][lk + ii][lm + 64] = f2tf(av1[ii]);
            Bs[buf][lk + ii][lm]      = f2tf(bv0[ii]);
            Bs[buf][lk + ii][lm + 64] = f2tf(bv1[ii]);
        }
    };

    {
        float4 a0 = *(const float4*)(Ap0);
        float4 a1 = *(const float4*)(Ap1);
        float4 b0 = *(const float4*)(Bp0);
        float4 b1 = *(const float4*)(Bp1);
        stage(0, a0, a1, b0, b1);
    }
    __syncthreads();

    int p = 0;
    for (int kt = 0; kt < K; kt += 16) {
        const bool more = (kt + 16) < K;
        float4 a0, a1, b0, b1;
        if (more) {
            a0 = *(const float4*)(Ap0 + kt + 16);
            a1 = *(const float4*)(Ap1 + kt + 16);
            b0 = *(const float4*)(Bp0 + kt + 16);
            b1 = *(const float4*)(Bp1 + kt + 16);
        }
        #pragma unroll
        for (int ks = 0; ks < 2; ++ks) {
            const int kk = ks * 8;
            unsigned af[2][4], bf[8][2];
            #pragma unroll
            for (int mt = 0; mt < 2; ++mt) {
                const int mr = wm + mt * 16 + grp;
                af[mt][0] = As[p][kk + qid][mr];
                af[mt][1] = As[p][kk + qid][mr + 8];
                af[mt][2] = As[p][kk + qid + 4][mr];
                af[mt][3] = As[p][kk + qid + 4][mr + 8];
            }
            #pragma unroll
            for (int nt = 0; nt < 8; ++nt) {
                const int nc = wn + nt * 8 + grp;
                bf[nt][0] = Bs[p][kk + qid][nc];
                bf[nt][1] = Bs[p][kk + qid + 4][nc];
            }
            #pragma unroll
            for (int mt = 0; mt < 2; ++mt)
                #pragma unroll
                for (int nt = 0; nt < 8; ++nt)
                    mma_tf32(acc[mt][nt], af[mt][0], af[mt][1], af[mt][2], af[mt][3],
                             bf[nt][0], bf[nt][1]);
        }
        if (more) {
            __syncthreads();
            stage(p ^ 1, a0, a1, b0, b1);
            __syncthreads();
            p ^= 1;
        }
    }

    // epilogue: c0/c1 -> (row, 2q), (row, 2q+1); c2/c3 -> row+8
    #pragma unroll
    for (int mt = 0; mt < 2; ++mt) {
        const int mr = m0 + wm + mt * 16 + grp;
        #pragma unroll
        for (int nt = 0; nt < 8; ++nt) {
            const int nc = n0 + wn + nt * 8 + 2 * qid;
            float2 b2 = make_float2(0.f, 0.f);
            if (BIAS) b2 = *(const float2*)(bias + nc);
            float2 v0, v1;
            v0.x = acc[mt][nt][0] + b2.x; v0.y = acc[mt][nt][1] + b2.y;
            v1.x = acc[mt][nt][2] + b2.x; v1.y = acc[mt][nt][3] + b2.y;
            *(float2*)(C + (size_t)mr * N + nc)       = v0;
            *(float2*)(C + (size_t)(mr + 8) * N + nc) = v1;
        }
    }
}

// ---------------- launcher --------------------------------------------------------
extern "C" void kernel_launch(void* const* d_in, const int* in_sizes, int n_in,
                              void* d_out, int out_size)
{
    const float* x     = (const float*)d_in[0];  // [T,B,DIN]
    const float* W_in  = (const float*)d_in[1];  // [DH,DIN]
    const float* U     = (const float*)d_in[2];  // [RANK,DH]
    const float* V     = (const float*)d_in[3];  // [DH,RANK]
    const float* b_h   = (const float*)d_in[4];  // [DH]
    const float* W_out = (const float*)d_in[5];  // [DOUT,DH]
    const float* b_out = (const float*)d_in[6];  // [DOUT]

    float* zi_ptr = nullptr;
    float* hscratch = nullptr;
    cudaGetSymbolAddress((void**)&zi_ptr, g_zi);
    cudaGetSymbolAddress((void**)&hscratch, g_hidden_scratch);

    const size_t HID_ELEMS = (size_t)T_SEQ * NBATCH * DH;
    const size_t OUT_ELEMS = (size_t)T_SEQ * NBATCH * DOUT;

    float* hidden_ptr;
    float* out_ptr;
    bool do_output = true;
    if ((size_t)out_size >= HID_ELEMS + OUT_ELEMS) {        // (hidden, output) concat
        hidden_ptr = (float*)d_out;
        out_ptr    = (float*)d_out + HID_ELEMS;
    } else if ((size_t)out_size == HID_ELEMS) {             // hidden only
        hidden_ptr = (float*)d_out;
        out_ptr    = nullptr;
        do_output  = false;
    } else {                                                // output only
        hidden_ptr = hscratch;
        out_ptr    = (float*)d_out;
    }

    const int M = T_SEQ * NBATCH;  // 65536

    // phase 1: zi = x @ W_in^T
    {
        dim3 grid(DH / 128, M / 128);
        gemm_tf32_nt<false><<<grid, 256>>>(x, W_in, nullptr, zi_ptr, M, DH, DIN);
    }
    // phase 2: recurrence (16 independent 8-CTA clusters, tf32 tensor cores)
    rnn_rec_tf32<<<128, 256>>>(U, V, b_h, zi_ptr, hidden_ptr);

    // phase 3: output = hidden @ W_out^T + b_out
    if (do_output) {
        dim3 grid(DOUT / 128, M / 128);
        gemm_tf32_nt<true><<<grid, 256>>>(hidden_ptr, W_out, b_out, out_ptr, M, DOUT, DH);
    }
}

// round 5
// speedup vs baseline: 3.0810x; 1.0794x over previous
#include <cuda_runtime.h>
#include <cstdint>

#define T_SEQ  512
#define NBATCH 128
#define DIN    256
#define DH     1024
#define NRANK  128
#define DOUT   256
#define BDH    (NBATCH * DH)

// ---------------- scratch ---------------------------------------------------------
__device__ float g_zi[(size_t)T_SEQ * NBATCH * DH];
__device__ float g_hidden_scratch[(size_t)T_SEQ * NBATCH * DH];
__device__ float g_Ppart[16 * 8 * 1024];   // [cluster][cta][r*8+b] stage1 partials

// ---------------- helpers ---------------------------------------------------------
__device__ __forceinline__ unsigned f2tf(float x)
{
    unsigned r;
    asm("cvt.rna.tf32.f32 %0, %1;" : "=r"(r) : "f"(x));
    return r;
}

__device__ __forceinline__ void mma_tf32(float c[4],
                                         unsigned a0, unsigned a1, unsigned a2, unsigned a3,
                                         unsigned b0, unsigned b1)
{
    asm volatile(
        "mma.sync.aligned.m16n8k8.row.col.f32.tf32.tf32.f32 "
        "{%0,%1,%2,%3}, {%4,%5,%6,%7}, {%8,%9}, {%0,%1,%2,%3};"
        : "+f"(c[0]), "+f"(c[1]), "+f"(c[2]), "+f"(c[3])
        : "r"(a0), "r"(a1), "r"(a2), "r"(a3), "r"(b0), "r"(b1));
}

__device__ __forceinline__ void cluster_sync()
{
    asm volatile("barrier.cluster.arrive.aligned;" ::: "memory");
    asm volatile("barrier.cluster.wait.aligned;" ::: "memory");
}

// ---------------- persistent recurrence kernel (tf32, 1 sync/step) ----------------
// 16 clusters x 8 CTAs. Cluster g owns batches [8g, 8g+8).
// CTA c owns DH-slice S_c = [128c, 128c+128) used BOTH as stage2 output j-slice and
// stage1 contraction k-slice -> h never leaves the SM; only P partials (4KB) cross.
//
// smem (unsigned words):
//   ufrag[16384]: U A-fragments, warp w / mma i / lane / ri  (LDS.128 per MMA)
//   vfrag[16384]: V A-fragments, same layout
//   hst  [1536] : h[b][j_local] as tf32, row stride 12 (8b + pad) -> conflict-free
//   pst  [1536] : P[r][b] as tf32, same layout
#define RSM_UFRAG 0
#define RSM_VFRAG 16384
#define RSM_HST   32768
#define RSM_PST   34304
#define RSM_WORDS 35840
#define RSM_BYTES (RSM_WORDS * 4)

__global__ void __cluster_dims__(8, 1, 1) __launch_bounds__(256, 1)
rnn_rec_tf32(const float* __restrict__ U, const float* __restrict__ V,
             const float* __restrict__ bh, const float* __restrict__ zi,
             float* __restrict__ hidden, float* __restrict__ ppart)
{
    extern __shared__ unsigned sm[];
    unsigned* ufrag = sm + RSM_UFRAG;
    unsigned* vfrag = sm + RSM_VFRAG;
    unsigned* hst   = sm + RSM_HST;
    unsigned* pst   = sm + RSM_PST;

    const int tid  = threadIdx.x;
    const int w    = tid >> 5;
    const int lane = tid & 31;
    const int grp  = lane >> 2;   // 0..7
    const int qid  = lane & 3;    // 0..3

    const int c   = blockIdx.x & 7;
    const int g   = blockIdx.x >> 3;
    const int b0g = g * 8;

    // ---- build ufrag: A = U[r 0..127][k_local 0..127], k_global = 128c + k_local
    // element (r,k): w_=r>>4, grp_=r&7, mh=(r>>3)&1; i=k>>3, qid_=k&3, kh=(k>>2)&1
    // word = ((w_*16+i)*32 + grp_*4 + qid_)*4 + (kh*2+mh)
    #pragma unroll
    for (int it = 0; it < 16; ++it) {
        const int f  = it * 256 + tid;
        const int r  = f >> 5;
        const int kq = f & 31;
        const float4 u4 = __ldg((const float4*)(U + (size_t)r * DH + c * 128 + kq * 4));
        const int w_ = r >> 4, grp_ = r & 7, mh = (r >> 3) & 1;
        const int i  = kq >> 1, kh = kq & 1;
        const unsigned base = (unsigned)(((w_ * 16 + i) * 32 + grp_ * 4) * 4 + kh * 2 + mh);
        ufrag[base + 0]  = f2tf(u4.x);
        ufrag[base + 4]  = f2tf(u4.y);
        ufrag[base + 8]  = f2tf(u4.z);
        ufrag[base + 12] = f2tf(u4.w);
    }
    // ---- build vfrag: A = V[j_local 0..127][r 0..127], j_global = 128c + j_local
    #pragma unroll
    for (int it = 0; it < 16; ++it) {
        const int f  = it * 256 + tid;
        const int jl = f >> 5;
        const int rq = f & 31;
        const float4 v4 = __ldg((const float4*)(V + (size_t)(c * 128 + jl) * NRANK + rq * 4));
        const int w_ = jl >> 4, grp_ = jl & 7, mh = (jl >> 3) & 1;
        const int i  = rq >> 1, kh = rq & 1;
        const unsigned base = (unsigned)(((w_ * 16 + i) * 32 + grp_ * 4) * 4 + kh * 2 + mh);
        vfrag[base + 0]  = f2tf(v4.x);
        vfrag[base + 4]  = f2tf(v4.y);
        vfrag[base + 8]  = f2tf(v4.z);
        vfrag[base + 12] = f2tf(v4.w);
    }
    // ---- init h(t=-1) = 0 in local smem
    #pragma unroll
    for (int it = 0; it < 6; ++it)
        hst[it * 256 + tid] = 0u;
    __syncthreads();

    // per-thread constants
    const int   jl0   = w * 16 + grp;                       // local j of c2[0]/c2[1]
    const float bias0 = __ldg(bh + c * 128 + jl0);
    const float bias1 = __ldg(bh + c * 128 + jl0 + 8);
    const size_t o00  = (size_t)(b0g + 2 * qid) * DH + c * 128 + jl0;
    float* const pp   = ppart + (size_t)(g * 8 + c) * 1024; // this CTA's partial bin
    const unsigned* const uf = ufrag + w * 2048;
    const unsigned* const vf = vfrag + w * 2048;

    for (int t = 0; t < T_SEQ; ++t) {
        // ---- zi prefetch (consumed at epilogue)
        const float* zit = zi + (size_t)t * BDH;
        const float z00 = __ldg(zit + o00);
        const float z01 = __ldg(zit + o00 + DH);
        const float z10 = __ldg(zit + o00 + 8);
        const float z11 = __ldg(zit + o00 + DH + 8);

        // ---- stage1: partial P over local k; warp w -> r-tile [16w,16w+16)
        float acc[4][4];
        #pragma unroll
        for (int a = 0; a < 4; ++a)
            #pragma unroll
            for (int j = 0; j < 4; ++j) acc[a][j] = 0.f;
        #pragma unroll
        for (int i = 0; i < 16; ++i) {
            const uint4 a4 = *(const uint4*)(uf + i * 128 + lane * 4);
            const unsigned b0 = hst[(8 * i + qid) * 12 + grp];
            const unsigned b1 = hst[(8 * i + qid + 4) * 12 + grp];
            mma_tf32(acc[i & 3], a4.x, a4.y, a4.z, a4.w, b0, b1);
        }
        {
            float c1[4];
            #pragma unroll
            for (int j = 0; j < 4; ++j)
                c1[j] = (acc[0][j] + acc[1][j]) + (acc[2][j] + acc[3][j]);
            const int r_ = w * 16 + grp;
            pp[r_ * 8 + 2 * qid]           = c1[0];
            pp[r_ * 8 + 2 * qid + 1]       = c1[1];
            pp[(r_ + 8) * 8 + 2 * qid]     = c1[2];
            pp[(r_ + 8) * 8 + 2 * qid + 1] = c1[3];
        }
        cluster_sync();   // partials visible cluster-wide

        // ---- gather + reduce 8 partials -> pst (tf32)
        {
            const int i4 = tid * 4;                       // r = i4>>3, b = i4&7 (0 or 4)
            const float* pb = ppart + (size_t)g * 8192 + i4;
            float4 s = __ldcg((const float4*)(pb));
            #pragma unroll
            for (int cc = 1; cc < 8; ++cc) {
                const float4 q = __ldcg((const float4*)(pb + cc * 1024));
                s.x += q.x; s.y += q.y; s.z += q.z; s.w += q.w;
            }
            const int r_ = i4 >> 3, b_ = i4 & 7;
            unsigned* d = pst + r_ * 12 + b_;
            d[0] = f2tf(s.x); d[1] = f2tf(s.y);
            d[2] = f2tf(s.z); d[3] = f2tf(s.w);
        }
        __syncthreads();

        // ---- stage2: h'[j-slice] = V_slice x P ; warp w -> j-tile [16w,16w+16)
        #pragma unroll
        for (int a = 0; a < 4; ++a)
            #pragma unroll
            for (int j = 0; j < 4; ++j) acc[a][j] = 0.f;
        #pragma unroll
        for (int i = 0; i < 16; ++i) {
            const uint4 a4 = *(const uint4*)(vf + i * 128 + lane * 4);
            const unsigned b0 = pst[(8 * i + qid) * 12 + grp];
            const unsigned b1 = pst[(8 * i + qid + 4) * 12 + grp];
            mma_tf32(acc[i & 3], a4.x, a4.y, a4.z, a4.w, b0, b1);
        }
        // ---- epilogue: + bias + zi, relu; store to hidden (global) and hst (local)
        {
            float c2[4];
            #pragma unroll
            for (int j = 0; j < 4; ++j)
                c2[j] = (acc[0][j] + acc[1][j]) + (acc[2][j] + acc[3][j]);
            const float h00 = fmaxf(c2[0] + bias0 + z00, 0.f);
            const float h01 = fmaxf(c2[1] + bias0 + z01, 0.f);
            const float h10 = fmaxf(c2[2] + bias1 + z10, 0.f);
            const float h11 = fmaxf(c2[3] + bias1 + z11, 0.f);
            float* ht = hidden + (size_t)t * BDH;
            ht[o00]          = h00;
            ht[o00 + DH]     = h01;
            ht[o00 + 8]      = h10;
            ht[o00 + DH + 8] = h11;
            hst[jl0 * 12 + 2 * qid]           = f2tf(h00);
            hst[jl0 * 12 + 2 * qid + 1]       = f2tf(h01);
            hst[(jl0 + 8) * 12 + 2 * qid]     = f2tf(h10);
            hst[(jl0 + 8) * 12 + 2 * qid + 1] = f2tf(h11);
        }
        __syncthreads();  // hst ready for next step's stage1
    }
}

// ---------------- tf32 NT GEMM: C[m,n] = sum_k A[m,k]*B[n,k] (+bias[n]) -----------
// BM=BN=128, BK=16, 256 threads, warp grid 4m x 2n, warp tile 32x64, m16n8k8.
template <bool BIAS>
__global__ void __launch_bounds__(256, 2)
gemm_tf32_nt(const float* __restrict__ A, const float* __restrict__ B,
             const float* __restrict__ bias, float* __restrict__ C,
             int M, int N, int K)
{
    __shared__ unsigned As[2][16][136];
    __shared__ unsigned Bs[2][16][136];

    const int tid  = threadIdx.x;
    const int wid  = tid >> 5;
    const int lane = tid & 31;
    const int grp  = lane >> 2;
    const int qid  = lane & 3;
    const int wm   = (wid >> 1) * 32;
    const int wn   = (wid & 1) * 64;
    const int m0   = blockIdx.y * 128;
    const int n0   = blockIdx.x * 128;
    const int lm   = tid >> 2;
    const int lk   = (tid & 3) << 2;
    const int lk4  = tid & 3;

    const float* Ap0 = A + (size_t)(m0 + lm) * K + lk;
    const float* Ap1 = Ap0 + (size_t)64 * K;
    const float* Bp0 = B + (size_t)(n0 + lm) * K + lk;
    const float* Bp1 = Bp0 + (size_t)64 * K;

    float acc[2][8][4];
    #pragma unroll
    for (int mt = 0; mt < 2; ++mt)
        #pragma unroll
        for (int nt = 0; nt < 8; ++nt)
            #pragma unroll
            for (int j = 0; j < 4; ++j) acc[mt][nt][j] = 0.f;

    auto stage = [&](int buf, const float4& a0, const float4& a1,
                     const float4& b0, const float4& b1) {
        float av0[4] = {a0.x, a0.y, a0.z, a0.w};
        float av1[4] = {a1.x, a1.y, a1.z, a1.w};
        float bv0[4] = {b0.x, b0.y, b0.z, b0.w};
        float bv1[4] = {b1.x, b1.y, b1.z, b1.w};
        #pragma unroll
        for (int i = 0; i < 4; ++i) {
            const int ii = (i + lk4) & 3;
            As[buf][lk + ii][lm]      = f2tf(av0[ii]);
            As[buf][lk + ii][lm + 64] = f2tf(av1[ii]);
            Bs[buf][lk + ii][lm]      = f2tf(bv0[ii]);
            Bs[buf][lk + ii][lm + 64] = f2tf(bv1[ii]);
        }
    };

    {
        float4 a0 = *(const float4*)(Ap0);
        float4 a1 = *(const float4*)(Ap1);
        float4 b0 = *(const float4*)(Bp0);
        float4 b1 = *(const float4*)(Bp1);
        stage(0, a0, a1, b0, b1);
    }
    __syncthreads();

    int p = 0;
    for (int kt = 0; kt < K; kt += 16) {
        const bool more = (kt + 16) < K;
        float4 a0, a1, b0, b1;
        if (more) {
            a0 = *(const float4*)(Ap0 + kt + 16);
            a1 = *(const float4*)(Ap1 + kt + 16);
            b0 = *(const float4*)(Bp0 + kt + 16);
            b1 = *(const float4*)(Bp1 + kt + 16);
        }
        #pragma unroll
        for (int ks = 0; ks < 2; ++ks) {
            const int kk = ks * 8;
            unsigned af[2][4], bf[8][2];
            #pragma unroll
            for (int mt = 0; mt < 2; ++mt) {
                const int mr = wm + mt * 16 + grp;
                af[mt][0] = As[p][kk + qid][mr];
                af[mt][1] = As[p][kk + qid][mr + 8];
                af[mt][2] = As[p][kk + qid + 4][mr];
                af[mt][3] = As[p][kk + qid + 4][mr + 8];
            }
            #pragma unroll
            for (int nt = 0; nt < 8; ++nt) {
                const int nc = wn + nt * 8 + grp;
                bf[nt][0] = Bs[p][kk + qid][nc];
                bf[nt][1] = Bs[p][kk + qid + 4][nc];
            }
            #pragma unroll
            for (int mt = 0; mt < 2; ++mt)
                #pragma unroll
                for (int nt = 0; nt < 8; ++nt)
                    mma_tf32(acc[mt][nt], af[mt][0], af[mt][1], af[mt][2], af[mt][3],
                             bf[nt][0], bf[nt][1]);
        }
        if (more) {
            __syncthreads();
            stage(p ^ 1, a0, a1, b0, b1);
            __syncthreads();
            p ^= 1;
        }
    }

    #pragma unroll
    for (int mt = 0; mt < 2; ++mt) {
        const int mr = m0 + wm + mt * 16 + grp;
        #pragma unroll
        for (int nt = 0; nt < 8; ++nt) {
            const int nc = n0 + wn + nt * 8 + 2 * qid;
            float2 b2 = make_float2(0.f, 0.f);
            if (BIAS) b2 = *(const float2*)(bias + nc);
            float2 v0, v1;
            v0.x = acc[mt][nt][0] + b2.x; v0.y = acc[mt][nt][1] + b2.y;
            v1.x = acc[mt][nt][2] + b2.x; v1.y = acc[mt][nt][3] + b2.y;
            *(float2*)(C + (size_t)mr * N + nc)       = v0;
            *(float2*)(C + (size_t)(mr + 8) * N + nc) = v1;
        }
    }
}

// ---------------- launcher --------------------------------------------------------
extern "C" void kernel_launch(void* const* d_in, const int* in_sizes, int n_in,
                              void* d_out, int out_size)
{
    const float* x     = (const float*)d_in[0];  // [T,B,DIN]
    const float* W_in  = (const float*)d_in[1];  // [DH,DIN]
    const float* U     = (const float*)d_in[2];  // [RANK,DH]
    const float* V     = (const float*)d_in[3];  // [DH,RANK]
    const float* b_h   = (const float*)d_in[4];  // [DH]
    const float* W_out = (const float*)d_in[5];  // [DOUT,DH]
    const float* b_out = (const float*)d_in[6];  // [DOUT]

    float* zi_ptr = nullptr;
    float* hscratch = nullptr;
    float* ppart = nullptr;
    cudaGetSymbolAddress((void**)&zi_ptr, g_zi);
    cudaGetSymbolAddress((void**)&hscratch, g_hidden_scratch);
    cudaGetSymbolAddress((void**)&ppart, g_Ppart);

    const size_t HID_ELEMS = (size_t)T_SEQ * NBATCH * DH;
    const size_t OUT_ELEMS = (size_t)T_SEQ * NBATCH * DOUT;

    float* hidden_ptr;
    float* out_ptr;
    bool do_output = true;
    if ((size_t)out_size >= HID_ELEMS + OUT_ELEMS) {        // (hidden, output) concat
        hidden_ptr = (float*)d_out;
        out_ptr    = (float*)d_out + HID_ELEMS;
    } else if ((size_t)out_size == HID_ELEMS) {             // hidden only
        hidden_ptr = (float*)d_out;
        out_ptr    = nullptr;
        do_output  = false;
    } else {                                                // output only
        hidden_ptr = hscratch;
        out_ptr    = (float*)d_out;
    }

    cudaFuncSetAttribute(rnn_rec_tf32,
                         cudaFuncAttributeMaxDynamicSharedMemorySize, RSM_BYTES);

    const int M = T_SEQ * NBATCH;  // 65536

    // phase 1: zi = x @ W_in^T
    {
        dim3 grid(DH / 128, M / 128);
        gemm_tf32_nt<false><<<grid, 256>>>(x, W_in, nullptr, zi_ptr, M, DH, DIN);
    }
    // phase 2: recurrence (16 clusters x 8 CTAs, 1 cluster sync per step)
    rnn_rec_tf32<<<128, 256, RSM_BYTES>>>(U, V, b_h, zi_ptr, hidden_ptr, ppart);

    // phase 3: output = hidden @ W_out^T + b_out
    if (do_output) {
        dim3 grid(DOUT / 128, M / 128);
        gemm_tf32_nt<true><<<grid, 256>>>(hidden_ptr, W_out, b_out, out_ptr, M, DOUT, DH);
    }
}

// round 6
// speedup vs baseline: 4.1251x; 1.3389x over previous
#include <cuda_runtime.h>
#include <cstdint>

#define T_SEQ  512
#define NBATCH 128
#define DIN    256
#define DH     1024
#define NRANK  128
#define DOUT   256
#define BDH    (NBATCH * DH)
#define NGRP   4          // batch groups per cluster

// ---------------- scratch ---------------------------------------------------------
__device__ float g_zi[(size_t)T_SEQ * NBATCH * DH];
__device__ float g_hidden_scratch[(size_t)T_SEQ * NBATCH * DH];
__device__ float g_Ppart[2 * 4 * 8 * 4096];   // [parity][cluster][cta][G*1024 + r*8+b]

// ---------------- helpers ---------------------------------------------------------
__device__ __forceinline__ unsigned f2tf(float x)
{
    unsigned r;
    asm("cvt.rna.tf32.f32 %0, %1;" : "=r"(r) : "f"(x));
    return r;
}

__device__ __forceinline__ void mma_tf32(float c[4],
                                         unsigned a0, unsigned a1, unsigned a2, unsigned a3,
                                         unsigned b0, unsigned b1)
{
    asm volatile(
        "mma.sync.aligned.m16n8k8.row.col.f32.tf32.tf32.f32 "
        "{%0,%1,%2,%3}, {%4,%5,%6,%7}, {%8,%9}, {%0,%1,%2,%3};"
        : "+f"(c[0]), "+f"(c[1]), "+f"(c[2]), "+f"(c[3])
        : "r"(a0), "r"(a1), "r"(a2), "r"(a3), "r"(b0), "r"(b1));
}

__device__ __forceinline__ void cluster_sync()
{
    asm volatile("barrier.cluster.arrive.aligned;" ::: "memory");
    asm volatile("barrier.cluster.wait.aligned;" ::: "memory");
}

// ---------------- persistent recurrence kernel ------------------------------------
// 4 clusters x 8 CTAs; cluster gg owns batches [32gg, 32gg+32) as 4 groups of 8.
// CTA c owns DH-slice [128c,128c+128) as BOTH stage2 j-slice and stage1 k-slice.
// One cluster_sync + one partial gather per step serves all 4 groups.
// smem: ufrag[16384] | vfrag[16384] | hst[4][1024] | pst[4][1024]  (words)
#define RSM_WORDS (16384 + 16384 + 4096 + 4096)
#define RSM_BYTES (RSM_WORDS * 4)

__global__ void __cluster_dims__(8, 1, 1) __launch_bounds__(256, 1)
rnn_rec_tf32(const float* __restrict__ U, const float* __restrict__ V,
             const float* __restrict__ bh, const float* __restrict__ zi,
             float* __restrict__ hidden, float* __restrict__ ppart)
{
    extern __shared__ unsigned sm[];
    unsigned* ufrag = sm;
    unsigned* vfrag = sm + 16384;
    unsigned* hst   = sm + 32768;          // 4 groups x [k*8+b]
    unsigned* pst   = sm + 32768 + 4096;   // 4 groups x [r*8+b]

    const int tid  = threadIdx.x;
    const int w    = tid >> 5;
    const int lane = tid & 31;
    const int grp  = lane >> 2;
    const int qid  = lane & 3;

    const int c   = blockIdx.x & 7;
    const int gg  = blockIdx.x >> 3;
    const int b0g = gg * 32;

    // ---- build ufrag: A = U[r 0..127][k_local 0..127], k_global = 128c + k_local
    #pragma unroll
    for (int it = 0; it < 16; ++it) {
        const int f  = it * 256 + tid;
        const int r  = f >> 5;
        const int kq = f & 31;
        const float4 u4 = __ldg((const float4*)(U + (size_t)r * DH + c * 128 + kq * 4));
        const int w_ = r >> 4, grp_ = r & 7, mh = (r >> 3) & 1;
        const int i  = kq >> 1, kh = kq & 1;
        const unsigned base = (unsigned)(((w_ * 16 + i) * 32 + grp_ * 4) * 4 + kh * 2 + mh);
        ufrag[base + 0]  = f2tf(u4.x);
        ufrag[base + 4]  = f2tf(u4.y);
        ufrag[base + 8]  = f2tf(u4.z);
        ufrag[base + 12] = f2tf(u4.w);
    }
    // ---- build vfrag: A = V[j_local 0..127][r 0..127], j_global = 128c + j_local
    #pragma unroll
    for (int it = 0; it < 16; ++it) {
        const int f  = it * 256 + tid;
        const int jl = f >> 5;
        const int rq = f & 31;
        const float4 v4 = __ldg((const float4*)(V + (size_t)(c * 128 + jl) * NRANK + rq * 4));
        const int w_ = jl >> 4, grp_ = jl & 7, mh = (jl >> 3) & 1;
        const int i  = rq >> 1, kh = rq & 1;
        const unsigned base = (unsigned)(((w_ * 16 + i) * 32 + grp_ * 4) * 4 + kh * 2 + mh);
        vfrag[base + 0]  = f2tf(v4.x);
        vfrag[base + 4]  = f2tf(v4.y);
        vfrag[base + 8]  = f2tf(v4.z);
        vfrag[base + 12] = f2tf(v4.w);
    }
    // ---- init h(t=-1) = 0
    #pragma unroll
    for (int it = 0; it < 16; ++it)
        hst[it * 256 + tid] = 0u;
    __syncthreads();

    const int   jl0   = w * 16 + grp;
    const float bias0 = __ldg(bh + c * 128 + jl0);
    const float bias1 = __ldg(bh + c * 128 + jl0 + 8);
    const unsigned* const uf = ufrag + w * 2048;
    const unsigned* const vf = vfrag + w * 2048;

    for (int t = 0; t < T_SEQ; ++t) {
        // ---- zi prefetch (all 4 groups), consumed at epilogue
        const float* zit = zi + (size_t)t * BDH;
        float z[NGRP][4];
        #pragma unroll
        for (int G = 0; G < NGRP; ++G) {
            const size_t base = (size_t)(b0g + 8 * G + 2 * qid) * DH + c * 128 + jl0;
            z[G][0] = __ldg(zit + base);
            z[G][1] = __ldg(zit + base + DH);
            z[G][2] = __ldg(zit + base + 8);
            z[G][3] = __ldg(zit + base + DH + 8);
        }

        // ---- stage1: P partials over local k, all 4 groups share A fragments
        float acc[NGRP][2][4];
        #pragma unroll
        for (int G = 0; G < NGRP; ++G)
            #pragma unroll
            for (int a = 0; a < 2; ++a)
                #pragma unroll
                for (int j = 0; j < 4; ++j) acc[G][a][j] = 0.f;
        #pragma unroll
        for (int i = 0; i < 16; ++i) {
            const uint4 a4 = *(const uint4*)(uf + i * 128 + lane * 4);
            #pragma unroll
            for (int G = 0; G < NGRP; ++G) {
                const unsigned b0 = hst[G * 1024 + (8 * i + qid) * 8 + grp];
                const unsigned b1 = hst[G * 1024 + (8 * i + qid + 4) * 8 + grp];
                mma_tf32(acc[G][i & 1], a4.x, a4.y, a4.z, a4.w, b0, b1);
            }
        }
        {
            float* pp = ppart + (size_t)((((t & 1) * 4 + gg) * 8) + c) * 4096;
            const int r_ = w * 16 + grp;
            #pragma unroll
            for (int G = 0; G < NGRP; ++G) {
                float c1[4];
                #pragma unroll
                for (int j = 0; j < 4; ++j)
                    c1[j] = acc[G][0][j] + acc[G][1][j];
                *(float2*)(pp + G * 1024 + r_ * 8 + 2 * qid)       = make_float2(c1[0], c1[1]);
                *(float2*)(pp + G * 1024 + (r_ + 8) * 8 + 2 * qid) = make_float2(c1[2], c1[3]);
            }
        }
        cluster_sync();   // partials visible cluster-wide

        // ---- gather: sum 8 CTA bins, all groups (32 independent LDG.128)
        {
            const float* gb = ppart + (size_t)((t & 1) * 4 + gg) * 8 * 4096 + 4 * tid;
            #pragma unroll
            for (int G = 0; G < NGRP; ++G) {
                float4 s = __ldcg((const float4*)(gb + G * 1024));
                #pragma unroll
                for (int cc = 1; cc < 8; ++cc) {
                    const float4 q = __ldcg((const float4*)(gb + cc * 4096 + G * 1024));
                    s.x += q.x; s.y += q.y; s.z += q.z; s.w += q.w;
                }
                uint4 d;
                d.x = f2tf(s.x); d.y = f2tf(s.y); d.z = f2tf(s.z); d.w = f2tf(s.w);
                *(uint4*)(pst + G * 1024 + 4 * tid) = d;
            }
        }
        __syncthreads();

        // ---- stage2: h' = V_slice x P, all 4 groups share A fragments
        #pragma unroll
        for (int G = 0; G < NGRP; ++G)
            #pragma unroll
            for (int a = 0; a < 2; ++a)
                #pragma unroll
                for (int j = 0; j < 4; ++j) acc[G][a][j] = 0.f;
        #pragma unroll
        for (int i = 0; i < 16; ++i) {
            const uint4 a4 = *(const uint4*)(vf + i * 128 + lane * 4);
            #pragma unroll
            for (int G = 0; G < NGRP; ++G) {
                const unsigned b0 = pst[G * 1024 + (8 * i + qid) * 8 + grp];
                const unsigned b1 = pst[G * 1024 + (8 * i + qid + 4) * 8 + grp];
                mma_tf32(acc[G][i & 1], a4.x, a4.y, a4.z, a4.w, b0, b1);
            }
        }
        // ---- epilogue: + bias + zi, relu; store hidden (global) + hst (local)
        {
            float* ht = hidden + (size_t)t * BDH;
            #pragma unroll
            for (int G = 0; G < NGRP; ++G) {
                float c2[4];
                #pragma unroll
                for (int j = 0; j < 4; ++j)
                    c2[j] = acc[G][0][j] + acc[G][1][j];
                const float h00 = fmaxf(c2[0] + bias0 + z[G][0], 0.f);
                const float h01 = fmaxf(c2[1] + bias0 + z[G][1], 0.f);
                const float h10 = fmaxf(c2[2] + bias1 + z[G][2], 0.f);
                const float h11 = fmaxf(c2[3] + bias1 + z[G][3], 0.f);
                const size_t base = (size_t)(b0g + 8 * G + 2 * qid) * DH + c * 128 + jl0;
                ht[base]          = h00;
                ht[base + DH]     = h01;
                ht[base + 8]      = h10;
                ht[base + DH + 8] = h11;
                hst[G * 1024 + jl0 * 8 + 2 * qid]           = f2tf(h00);
                hst[G * 1024 + jl0 * 8 + 2 * qid + 1]       = f2tf(h01);
                hst[G * 1024 + (jl0 + 8) * 8 + 2 * qid]     = f2tf(h10);
                hst[G * 1024 + (jl0 + 8) * 8 + 2 * qid + 1] = f2tf(h11);
            }
        }
        __syncthreads();  // hst ready for next step
    }
}

// ---------------- tf32 NT GEMM (swizzled, spill-free) -----------------------------
// C[m,n] = sum_k A[m,k]*B[n,k] (+bias[n]); BM=BN=128, BK=16, 256 thr, m16n8k8.
// Element (k,m) stored at col m ^ (8*((k>>2)&3)): conflict-free stores AND reads.
template <bool BIAS>
__global__ void __launch_bounds__(256, 2)
gemm_tf32_nt(const float* __restrict__ A, const float* __restrict__ B,
             const float* __restrict__ bias, float* __restrict__ C,
             int M, int N, int K)
{
    __shared__ unsigned As[2][16][136];
    __shared__ unsigned Bs[2][16][136];

    const int tid  = threadIdx.x;
    const int wid  = tid >> 5;
    const int lane = tid & 31;
    const int grp  = lane >> 2;
    const int qid  = lane & 3;
    const int wm   = (wid >> 1) * 32;
    const int wn   = (wid & 1) * 64;
    const int m0   = blockIdx.y * 128;
    const int n0   = blockIdx.x * 128;
    const int lm   = tid >> 2;
    const int lk   = (tid & 3) << 2;
    const int lk4  = tid & 3;
    const int cm0  = lm ^ (lk4 * 8);     // swizzled store col (low half)

    const float* Ap0 = A + (size_t)(m0 + lm) * K + lk;
    const float* Ap1 = Ap0 + (size_t)64 * K;
    const float* Bp0 = B + (size_t)(n0 + lm) * K + lk;
    const float* Bp1 = Bp0 + (size_t)64 * K;

    float acc[2][8][4];
    #pragma unroll
    for (int mt = 0; mt < 2; ++mt)
        #pragma unroll
        for (int nt = 0; nt < 8; ++nt)
            #pragma unroll
            for (int j = 0; j < 4; ++j) acc[mt][nt][j] = 0.f;

    auto stage = [&](int buf, const float4& a0, const float4& a1,
                     const float4& b0, const float4& b1) {
        As[buf][lk + 0][cm0]      = f2tf(a0.x);
        As[buf][lk + 1][cm0]      = f2tf(a0.y);
        As[buf][lk + 2][cm0]      = f2tf(a0.z);
        As[buf][lk + 3][cm0]      = f2tf(a0.w);
        As[buf][lk + 0][cm0 + 64] = f2tf(a1.x);
        As[buf][lk + 1][cm0 + 64] = f2tf(a1.y);
        As[buf][lk + 2][cm0 + 64] = f2tf(a1.z);
        As[buf][lk + 3][cm0 + 64] = f2tf(a1.w);
        Bs[buf][lk + 0][cm0]      = f2tf(b0.x);
        Bs[buf][lk + 1][cm0]      = f2tf(b0.y);
        Bs[buf][lk + 2][cm0]      = f2tf(b0.z);
        Bs[buf][lk + 3][cm0]      = f2tf(b0.w);
        Bs[buf][lk + 0][cm0 + 64] = f2tf(b1.x);
        Bs[buf][lk + 1][cm0 + 64] = f2tf(b1.y);
        Bs[buf][lk + 2][cm0 + 64] = f2tf(b1.z);
        Bs[buf][lk + 3][cm0 + 64] = f2tf(b1.w);
    };

    {
        float4 a0 = *(const float4*)(Ap0);
        float4 a1 = *(const float4*)(Ap1);
        float4 b0 = *(const float4*)(Bp0);
        float4 b1 = *(const float4*)(Bp1);
        stage(0, a0, a1, b0, b1);
    }
    __syncthreads();

    int p = 0;
    for (int kt = 0; kt < K; kt += 16) {
        const bool more = (kt + 16) < K;
        float4 a0, a1, b0, b1;
        if (more) {
            a0 = *(const float4*)(Ap0 + kt + 16);
            a1 = *(const float4*)(Ap1 + kt + 16);
            b0 = *(const float4*)(Bp0 + kt + 16);
            b1 = *(const float4*)(Bp1 + kt + 16);
        }
        #pragma unroll
        for (int ks = 0; ks < 2; ++ks) {
            const int kk = ks * 8;
            const int s0 = (ks == 0) ? 0  : 16;   // swizzle for rows kk+qid
            const int s1 = (ks == 0) ? 8  : 24;   // swizzle for rows kk+qid+4
            unsigned af[2][4], bf[8][2];
            #pragma unroll
            for (int mt = 0; mt < 2; ++mt) {
                const int mr = wm + mt * 16 + grp;
                af[mt][0] = As[p][kk + qid][mr ^ s0];
                af[mt][1] = As[p][kk + qid][(mr + 8) ^ s0];
                af[mt][2] = As[p][kk + qid + 4][mr ^ s1];
                af[mt][3] = As[p][kk + qid + 4][(mr + 8) ^ s1];
            }
            #pragma unroll
            for (int nt = 0; nt < 8; ++nt) {
                const int nc = wn + nt * 8 + grp;
                bf[nt][0] = Bs[p][kk + qid][nc ^ s0];
                bf[nt][1] = Bs[p][kk + qid + 4][nc ^ s1];
            }
            #pragma unroll
            for (int mt = 0; mt < 2; ++mt)
                #pragma unroll
                for (int nt = 0; nt < 8; ++nt)
                    mma_tf32(acc[mt][nt], af[mt][0], af[mt][1], af[mt][2], af[mt][3],
                             bf[nt][0], bf[nt][1]);
        }
        if (more) {
            __syncthreads();
            stage(p ^ 1, a0, a1, b0, b1);
            __syncthreads();
            p ^= 1;
        }
    }

    #pragma unroll
    for (int mt = 0; mt < 2; ++mt) {
        const int mr = m0 + wm + mt * 16 + grp;
        #pragma unroll
        for (int nt = 0; nt < 8; ++nt) {
            const int nc = n0 + wn + nt * 8 + 2 * qid;
            float2 b2 = make_float2(0.f, 0.f);
            if (BIAS) b2 = *(const float2*)(bias + nc);
            float2 v0, v1;
            v0.x = acc[mt][nt][0] + b2.x; v0.y = acc[mt][nt][1] + b2.y;
            v1.x = acc[mt][nt][2] + b2.x; v1.y = acc[mt][nt][3] + b2.y;
            *(float2*)(C + (size_t)mr * N + nc)       = v0;
            *(float2*)(C + (size_t)(mr + 8) * N + nc) = v1;
        }
    }
}

// ---------------- launcher --------------------------------------------------------
extern "C" void kernel_launch(void* const* d_in, const int* in_sizes, int n_in,
                              void* d_out, int out_size)
{
    const float* x     = (const float*)d_in[0];  // [T,B,DIN]
    const float* W_in  = (const float*)d_in[1];  // [DH,DIN]
    const float* U     = (const float*)d_in[2];  // [RANK,DH]
    const float* V     = (const float*)d_in[3];  // [DH,RANK]
    const float* b_h   = (const float*)d_in[4];  // [DH]
    const float* W_out = (const float*)d_in[5];  // [DOUT,DH]
    const float* b_out = (const float*)d_in[6];  // [DOUT]

    float* zi_ptr = nullptr;
    float* hscratch = nullptr;
    float* ppart = nullptr;
    cudaGetSymbolAddress((void**)&zi_ptr, g_zi);
    cudaGetSymbolAddress((void**)&hscratch, g_hidden_scratch);
    cudaGetSymbolAddress((void**)&ppart, g_Ppart);

    const size_t HID_ELEMS = (size_t)T_SEQ * NBATCH * DH;
    const size_t OUT_ELEMS = (size_t)T_SEQ * NBATCH * DOUT;

    float* hidden_ptr;
    float* out_ptr;
    bool do_output = true;
    if ((size_t)out_size >= HID_ELEMS + OUT_ELEMS) {        // (hidden, output) concat
        hidden_ptr = (float*)d_out;
        out_ptr    = (float*)d_out + HID_ELEMS;
    } else if ((size_t)out_size == HID_ELEMS) {             // hidden only
        hidden_ptr = (float*)d_out;
        out_ptr    = nullptr;
        do_output  = false;
    } else {                                                // output only
        hidden_ptr = hscratch;
        out_ptr    = (float*)d_out;
    }

    cudaFuncSetAttribute(rnn_rec_tf32,
                         cudaFuncAttributeMaxDynamicSharedMemorySize, RSM_BYTES);

    const int M = T_SEQ * NBATCH;  // 65536

    // phase 1: zi = x @ W_in^T
    {
        dim3 grid(DH / 128, M / 128);
        gemm_tf32_nt<false><<<grid, 256>>>(x, W_in, nullptr, zi_ptr, M, DH, DIN);
    }
    // phase 2: recurrence (4 clusters x 8 CTAs, 4 batch-groups per cluster)
    rnn_rec_tf32<<<32, 256, RSM_BYTES>>>(U, V, b_h, zi_ptr, hidden_ptr, ppart);

    // phase 3: output = hidden @ W_out^T + b_out
    if (do_output) {
        dim3 grid(DOUT / 128, M / 128);
        gemm_tf32_nt<true><<<grid, 256>>>(hidden_ptr, W_out, b_out, out_ptr, M, DOUT, DH);
    }
}

// round 7
// speedup vs baseline: 5.5038x; 1.3342x over previous
#include <cuda_runtime.h>
#include <cstdint>

#define T_SEQ  512
#define NBATCH 128
#define DIN    256
#define DH     1024
#define NRANK  128
#define DOUT   256
#define BDH    (NBATCH * DH)
#define NGRP   2          // batch groups per cluster
#define NCLUS  8          // clusters

// ---------------- scratch ---------------------------------------------------------
__device__ float g_zi[(size_t)T_SEQ * NBATCH * DH];
__device__ float g_hidden_scratch[(size_t)T_SEQ * NBATCH * DH];
__device__ float g_Ppart[2 * NCLUS * 16 * 2048];  // [parity][cluster][bin16][G*1024+r*8+b]

// ---------------- helpers ---------------------------------------------------------
__device__ __forceinline__ unsigned f2tf(float x)
{
    unsigned r;
    asm("cvt.rna.tf32.f32 %0, %1;" : "=r"(r) : "f"(x));
    return r;
}

__device__ __forceinline__ void mma_tf32(float c[4],
                                         unsigned a0, unsigned a1, unsigned a2, unsigned a3,
                                         unsigned b0, unsigned b1)
{
    asm volatile(
        "mma.sync.aligned.m16n8k8.row.col.f32.tf32.tf32.f32 "
        "{%0,%1,%2,%3}, {%4,%5,%6,%7}, {%8,%9}, {%0,%1,%2,%3};"
        : "+f"(c[0]), "+f"(c[1]), "+f"(c[2]), "+f"(c[3])
        : "r"(a0), "r"(a1), "r"(a2), "r"(a3), "r"(b0), "r"(b1));
}

__device__ __forceinline__ void cluster_sync()
{
    asm volatile("barrier.cluster.arrive.aligned;" ::: "memory");
    asm volatile("barrier.cluster.wait.aligned;" ::: "memory");
}

// ---------------- persistent recurrence kernel ------------------------------------
// 8 clusters x 8 CTAs; cluster gg owns batches [16gg, 16gg+16) as 2 groups of 8.
// CTA c owns DH-slice [128c,128c+128) as BOTH stage2 j-slice and stage1 k-slice.
// Warp (kh = w>>2, wq = w&3): computes 32 output rows [32wq,32wq+32) over K-half kh
// -> each B-fragment pair feeds 2 MMAs (B smem traffic halved vs 16-row warps).
// Stage1 kh-halves stored as separate gmem bins (gather sums 16 bins);
// stage2 kh=1 half reduced through smem `red` (output is CTA-local).
// smem (words): ufrag 16384 | vfrag 16384 | hst 2048 | pst 2048 | red 2048
#define RSM_WORDS (16384 + 16384 + 2048 + 2048 + 2048)
#define RSM_BYTES (RSM_WORDS * 4)

__global__ void __cluster_dims__(8, 1, 1) __launch_bounds__(256, 1)
rnn_rec_tf32(const float* __restrict__ U, const float* __restrict__ V,
             const float* __restrict__ bh, const float* __restrict__ zi,
             float* __restrict__ hidden, float* __restrict__ ppart)
{
    extern __shared__ unsigned sm[];
    unsigned* ufrag = sm;
    unsigned* vfrag = sm + 16384;
    unsigned* hst   = sm + 32768;          // [G][k*8 + b]
    unsigned* pst   = sm + 32768 + 2048;   // [G][r*8 + b]
    float*    red   = (float*)(sm + 32768 + 4096);  // [G][j*8 + b]

    const int tid  = threadIdx.x;
    const int w    = tid >> 5;
    const int lane = tid & 31;
    const int grp  = lane >> 2;
    const int qid  = lane & 3;
    const int kh   = w >> 2;     // K-half
    const int wq   = w & 3;      // 32-row tile

    const int c   = blockIdx.x & 7;
    const int gg  = blockIdx.x >> 3;
    const int b0g = gg * 16;

    // ---- build ufrag: A = U[r 0..127][k_local 0..127]; frame(a=r>>4, i8=k>>3)
    #pragma unroll
    for (int it = 0; it < 16; ++it) {
        const int f  = it * 256 + tid;
        const int r  = f >> 5;
        const int kq = f & 31;
        const float4 u4 = __ldg((const float4*)(U + (size_t)r * DH + c * 128 + kq * 4));
        const int a_ = r >> 4, grp_ = r & 7, mh = (r >> 3) & 1;
        const int i8 = kq >> 1, khw = kq & 1;
        const unsigned base = (unsigned)(((a_ * 16 + i8) * 32 + grp_ * 4) * 4 + khw * 2 + mh);
        ufrag[base + 0]  = f2tf(u4.x);
        ufrag[base + 4]  = f2tf(u4.y);
        ufrag[base + 8]  = f2tf(u4.z);
        ufrag[base + 12] = f2tf(u4.w);
    }
    // ---- build vfrag: A = V[j_local 0..127][r 0..127]; frame(a=j>>4, i8=r>>3)
    #pragma unroll
    for (int it = 0; it < 16; ++it) {
        const int f  = it * 256 + tid;
        const int jl = f >> 5;
        const int rq = f & 31;
        const float4 v4 = __ldg((const float4*)(V + (size_t)(c * 128 + jl) * NRANK + rq * 4));
        const int a_ = jl >> 4, grp_ = jl & 7, mh = (jl >> 3) & 1;
        const int i8 = rq >> 1, khw = rq & 1;
        const unsigned base = (unsigned)(((a_ * 16 + i8) * 32 + grp_ * 4) * 4 + khw * 2 + mh);
        vfrag[base + 0]  = f2tf(v4.x);
        vfrag[base + 4]  = f2tf(v4.y);
        vfrag[base + 8]  = f2tf(v4.z);
        vfrag[base + 12] = f2tf(v4.w);
    }
    // ---- init h(t=-1) = 0
    #pragma unroll
    for (int it = 0; it < 8; ++it)
        hst[it * 256 + tid] = 0u;
    __syncthreads();

    // warp-local fragment bases: frames (2wq, kh*8 + i) and (2wq+1, kh*8 + i)
    const unsigned* const ufA = ufrag + (2 * wq * 16 + kh * 8) * 128 + lane * 4;
    const unsigned* const vfA = vfrag + (2 * wq * 16 + kh * 8) * 128 + lane * 4;

    // epilogue constants (kh==0 warps)
    float bias_[2][2];
    #pragma unroll
    for (int mh = 0; mh < 2; ++mh)
        #pragma unroll
        for (int rh = 0; rh < 2; ++rh)
            bias_[mh][rh] = __ldg(bh + c * 128 + 32 * wq + 16 * mh + grp + 8 * rh);

    for (int t = 0; t < T_SEQ; ++t) {
        // ---- zi prefetch (kh==0 warps only; consumed at epilogue)
        float z[NGRP][2][4];
        if (kh == 0) {
            const float* zit = zi + (size_t)t * BDH;
            #pragma unroll
            for (int G = 0; G < NGRP; ++G)
                #pragma unroll
                for (int mh = 0; mh < 2; ++mh) {
                    const size_t base = (size_t)(b0g + 8 * G + 2 * qid) * DH
                                      + c * 128 + 32 * wq + 16 * mh + grp;
                    z[G][mh][0] = __ldg(zit + base);
                    z[G][mh][1] = __ldg(zit + base + DH);
                    z[G][mh][2] = __ldg(zit + base + 8);
                    z[G][mh][3] = __ldg(zit + base + DH + 8);
                }
        }

        // ---- stage1: partial P over K-half kh; rows [32wq, 32wq+32)
        float s1[NGRP][2][4];
        #pragma unroll
        for (int G = 0; G < NGRP; ++G)
            #pragma unroll
            for (int mh = 0; mh < 2; ++mh)
                #pragma unroll
                for (int j = 0; j < 4; ++j) s1[G][mh][j] = 0.f;
        #pragma unroll
        for (int i = 0; i < 8; ++i) {
            const uint4 aA = *(const uint4*)(ufA + i * 128);
            const uint4 aB = *(const uint4*)(ufA + i * 128 + 2048);
            const int kk = kh * 64 + 8 * i;
            #pragma unroll
            for (int G = 0; G < NGRP; ++G) {
                const unsigned b0 = hst[G * 1024 + (kk + qid) * 8 + grp];
                const unsigned b1 = hst[G * 1024 + (kk + qid + 4) * 8 + grp];
                mma_tf32(s1[G][0], aA.x, aA.y, aA.z, aA.w, b0, b1);
                mma_tf32(s1[G][1], aB.x, aB.y, aB.z, aB.w, b0, b1);
            }
        }
        // ---- store this warp's partial into bin (c*2 + kh)
        {
            float* pp = ppart + (size_t)((((t & 1) * NCLUS + gg) * 16) + c * 2 + kh) * 2048;
            #pragma unroll
            for (int G = 0; G < NGRP; ++G)
                #pragma unroll
                for (int mh = 0; mh < 2; ++mh) {
                    const int r_ = 32 * wq + 16 * mh + grp;
                    *(float2*)(pp + G * 1024 + r_ * 8 + 2 * qid) =
                        make_float2(s1[G][mh][0], s1[G][mh][1]);
                    *(float2*)(pp + G * 1024 + (r_ + 8) * 8 + 2 * qid) =
                        make_float2(s1[G][mh][2], s1[G][mh][3]);
                }
        }
        cluster_sync();   // partials visible cluster-wide

        // ---- gather: sum 16 bins -> pst (tf32)
        {
            const float* gb = ppart + (size_t)((t & 1) * NCLUS + gg) * 16 * 2048;
            #pragma unroll
            for (int jj = 0; jj < 2; ++jj) {
                const int o4 = (tid + 256 * jj) * 4;
                float4 s = __ldcg((const float4*)(gb + o4));
                #pragma unroll
                for (int bb = 1; bb < 16; ++bb) {
                    const float4 q = __ldcg((const float4*)(gb + bb * 2048 + o4));
                    s.x += q.x; s.y += q.y; s.z += q.z; s.w += q.w;
                }
                uint4 d;
                d.x = f2tf(s.x); d.y = f2tf(s.y); d.z = f2tf(s.z); d.w = f2tf(s.w);
                *(uint4*)(pst + o4) = d;
            }
        }
        __syncthreads();

        // ---- stage2: h' partial over r-half kh; rows [32wq, 32wq+32)
        float s2[NGRP][2][4];
        #pragma unroll
        for (int G = 0; G < NGRP; ++G)
            #pragma unroll
            for (int mh = 0; mh < 2; ++mh)
                #pragma unroll
                for (int j = 0; j < 4; ++j) s2[G][mh][j] = 0.f;
        #pragma unroll
        for (int i = 0; i < 8; ++i) {
            const uint4 aA = *(const uint4*)(vfA + i * 128);
            const uint4 aB = *(const uint4*)(vfA + i * 128 + 2048);
            const int kk = kh * 64 + 8 * i;
            #pragma unroll
            for (int G = 0; G < NGRP; ++G) {
                const unsigned b0 = pst[G * 1024 + (kk + qid) * 8 + grp];
                const unsigned b1 = pst[G * 1024 + (kk + qid + 4) * 8 + grp];
                mma_tf32(s2[G][0], aA.x, aA.y, aA.z, aA.w, b0, b1);
                mma_tf32(s2[G][1], aB.x, aB.y, aB.z, aB.w, b0, b1);
            }
        }
        // ---- kh=1 half -> smem red
        if (kh == 1) {
            #pragma unroll
            for (int G = 0; G < NGRP; ++G)
                #pragma unroll
                for (int mh = 0; mh < 2; ++mh) {
                    const int jl = 32 * wq + 16 * mh + grp;
                    red[G * 1024 + jl * 8 + 2 * qid]           = s2[G][mh][0];
                    red[G * 1024 + jl * 8 + 2 * qid + 1]       = s2[G][mh][1];
                    red[G * 1024 + (jl + 8) * 8 + 2 * qid]     = s2[G][mh][2];
                    red[G * 1024 + (jl + 8) * 8 + 2 * qid + 1] = s2[G][mh][3];
                }
        }
        __syncthreads();
        // ---- epilogue (kh==0 warps): sum halves, + bias + zi, relu, store
        if (kh == 0) {
            float* ht = hidden + (size_t)t * BDH;
            #pragma unroll
            for (int G = 0; G < NGRP; ++G)
                #pragma unroll
                for (int mh = 0; mh < 2; ++mh) {
                    const int jl = 32 * wq + 16 * mh + grp;
                    const float r00 = red[G * 1024 + jl * 8 + 2 * qid];
                    const float r01 = red[G * 1024 + jl * 8 + 2 * qid + 1];
                    const float r10 = red[G * 1024 + (jl + 8) * 8 + 2 * qid];
                    const float r11 = red[G * 1024 + (jl + 8) * 8 + 2 * qid + 1];
                    const float h00 = fmaxf(s2[G][mh][0] + r00 + bias_[mh][0] + z[G][mh][0], 0.f);
                    const float h01 = fmaxf(s2[G][mh][1] + r01 + bias_[mh][0] + z[G][mh][1], 0.f);
                    const float h10 = fmaxf(s2[G][mh][2] + r10 + bias_[mh][1] + z[G][mh][2], 0.f);
                    const float h11 = fmaxf(s2[G][mh][3] + r11 + bias_[mh][1] + z[G][mh][3], 0.f);
                    const size_t base = (size_t)(b0g + 8 * G + 2 * qid) * DH + c * 128 + jl;
                    ht[base]          = h00;
                    ht[base + DH]     = h01;
                    ht[base + 8]      = h10;
                    ht[base + DH + 8] = h11;
                    hst[G * 1024 + jl * 8 + 2 * qid]           = f2tf(h00);
                    hst[G * 1024 + jl * 8 + 2 * qid + 1]       = f2tf(h01);
                    hst[G * 1024 + (jl + 8) * 8 + 2 * qid]     = f2tf(h10);
                    hst[G * 1024 + (jl + 8) * 8 + 2 * qid + 1] = f2tf(h11);
                }
        }
        __syncthreads();  // hst ready for next step
    }
}

// ---------------- tf32 NT GEMM (swizzled, spill-free) -----------------------------
template <bool BIAS>
__global__ void __launch_bounds__(256, 2)
gemm_tf32_nt(const float* __restrict__ A, const float* __restrict__ B,
             const float* __restrict__ bias, float* __restrict__ C,
             int M, int N, int K)
{
    __shared__ unsigned As[2][16][136];
    __shared__ unsigned Bs[2][16][136];

    const int tid  = threadIdx.x;
    const int wid  = tid >> 5;
    const int lane = tid & 31;
    const int grp  = lane >> 2;
    const int qid  = lane & 3;
    const int wm   = (wid >> 1) * 32;
    const int wn   = (wid & 1) * 64;
    const int m0   = blockIdx.y * 128;
    const int n0   = blockIdx.x * 128;
    const int lm   = tid >> 2;
    const int lk   = (tid & 3) << 2;
    const int lk4  = tid & 3;
    const int cm0  = lm ^ (lk4 * 8);

    const float* Ap0 = A + (size_t)(m0 + lm) * K + lk;
    const float* Ap1 = Ap0 + (size_t)64 * K;
    const float* Bp0 = B + (size_t)(n0 + lm) * K + lk;
    const float* Bp1 = Bp0 + (size_t)64 * K;

    float acc[2][8][4];
    #pragma unroll
    for (int mt = 0; mt < 2; ++mt)
        #pragma unroll
        for (int nt = 0; nt < 8; ++nt)
            #pragma unroll
            for (int j = 0; j < 4; ++j) acc[mt][nt][j] = 0.f;

    auto stage = [&](int buf, const float4& a0, const float4& a1,
                     const float4& b0, const float4& b1) {
        As[buf][lk + 0][cm0]      = f2tf(a0.x);
        As[buf][lk + 1][cm0]      = f2tf(a0.y);
        As[buf][lk + 2][cm0]      = f2tf(a0.z);
        As[buf][lk + 3][cm0]      = f2tf(a0.w);
        As[buf][lk + 0][cm0 + 64] = f2tf(a1.x);
        As[buf][lk + 1][cm0 + 64] = f2tf(a1.y);
        As[buf][lk + 2][cm0 + 64] = f2tf(a1.z);
        As[buf][lk + 3][cm0 + 64] = f2tf(a1.w);
        Bs[buf][lk + 0][cm0]      = f2tf(b0.x);
        Bs[buf][lk + 1][cm0]      = f2tf(b0.y);
        Bs[buf][lk + 2][cm0]      = f2tf(b0.z);
        Bs[buf][lk + 3][cm0]      = f2tf(b0.w);
        Bs[buf][lk + 0][cm0 + 64] = f2tf(b1.x);
        Bs[buf][lk + 1][cm0 + 64] = f2tf(b1.y);
        Bs[buf][lk + 2][cm0 + 64] = f2tf(b1.z);
        Bs[buf][lk + 3][cm0 + 64] = f2tf(b1.w);
    };

    {
        float4 a0 = *(const float4*)(Ap0);
        float4 a1 = *(const float4*)(Ap1);
        float4 b0 = *(const float4*)(Bp0);
        float4 b1 = *(const float4*)(Bp1);
        stage(0, a0, a1, b0, b1);
    }
    __syncthreads();

    int p = 0;
    for (int kt = 0; kt < K; kt += 16) {
        const bool more = (kt + 16) < K;
        float4 a0, a1, b0, b1;
        if (more) {
            a0 = *(const float4*)(Ap0 + kt + 16);
            a1 = *(const float4*)(Ap1 + kt + 16);
            b0 = *(const float4*)(Bp0 + kt + 16);
            b1 = *(const float4*)(Bp1 + kt + 16);
        }
        #pragma unroll
        for (int ks = 0; ks < 2; ++ks) {
            const int kk = ks * 8;
            const int s0 = (ks == 0) ? 0  : 16;
            const int s1 = (ks == 0) ? 8  : 24;
            unsigned af[2][4], bf[8][2];
            #pragma unroll
            for (int mt = 0; mt < 2; ++mt) {
                const int mr = wm + mt * 16 + grp;
                af[mt][0] = As[p][kk + qid][mr ^ s0];
                af[mt][1] = As[p][kk + qid][(mr + 8) ^ s0];
                af[mt][2] = As[p][kk + qid + 4][mr ^ s1];
                af[mt][3] = As[p][kk + qid + 4][(mr + 8) ^ s1];
            }
            #pragma unroll
            for (int nt = 0; nt < 8; ++nt) {
                const int nc = wn + nt * 8 + grp;
                bf[nt][0] = Bs[p][kk + qid][nc ^ s0];
                bf[nt][1] = Bs[p][kk + qid + 4][nc ^ s1];
            }
            #pragma unroll
            for (int mt = 0; mt < 2; ++mt)
                #pragma unroll
                for (int nt = 0; nt < 8; ++nt)
                    mma_tf32(acc[mt][nt], af[mt][0], af[mt][1], af[mt][2], af[mt][3],
                             bf[nt][0], bf[nt][1]);
        }
        if (more) {
            __syncthreads();
            stage(p ^ 1, a0, a1, b0, b1);
            __syncthreads();
            p ^= 1;
        }
    }

    #pragma unroll
    for (int mt = 0; mt < 2; ++mt) {
        const int mr = m0 + wm + mt * 16 + grp;
        #pragma unroll
        for (int nt = 0; nt < 8; ++nt) {
            const int nc = n0 + wn + nt * 8 + 2 * qid;
            float2 b2 = make_float2(0.f, 0.f);
            if (BIAS) b2 = *(const float2*)(bias + nc);
            float2 v0, v1;
            v0.x = acc[mt][nt][0] + b2.x; v0.y = acc[mt][nt][1] + b2.y;
            v1.x = acc[mt][nt][2] + b2.x; v1.y = acc[mt][nt][3] + b2.y;
            *(float2*)(C + (size_t)mr * N + nc)       = v0;
            *(float2*)(C + (size_t)(mr + 8) * N + nc) = v1;
        }
    }
}

// ---------------- launcher --------------------------------------------------------
extern "C" void kernel_launch(void* const* d_in, const int* in_sizes, int n_in,
                              void* d_out, int out_size)
{
    const float* x     = (const float*)d_in[0];  // [T,B,DIN]
    const float* W_in  = (const float*)d_in[1];  // [DH,DIN]
    const float* U     = (const float*)d_in[2];  // [RANK,DH]
    const float* V     = (const float*)d_in[3];  // [DH,RANK]
    const float* b_h   = (const float*)d_in[4];  // [DH]
    const float* W_out = (const float*)d_in[5];  // [DOUT,DH]
    const float* b_out = (const float*)d_in[6];  // [DOUT]

    float* zi_ptr = nullptr;
    float* hscratch = nullptr;
    float* ppart = nullptr;
    cudaGetSymbolAddress((void**)&zi_ptr, g_zi);
    cudaGetSymbolAddress((void**)&hscratch, g_hidden_scratch);
    cudaGetSymbolAddress((void**)&ppart, g_Ppart);

    const size_t HID_ELEMS = (size_t)T_SEQ * NBATCH * DH;
    const size_t OUT_ELEMS = (size_t)T_SEQ * NBATCH * DOUT;

    float* hidden_ptr;
    float* out_ptr;
    bool do_output = true;
    if ((size_t)out_size >= HID_ELEMS + OUT_ELEMS) {        // (hidden, output) concat
        hidden_ptr = (float*)d_out;
        out_ptr    = (float*)d_out + HID_ELEMS;
    } else if ((size_t)out_size == HID_ELEMS) {             // hidden only
        hidden_ptr = (float*)d_out;
        out_ptr    = nullptr;
        do_output  = false;
    } else {                                                // output only
        hidden_ptr = hscratch;
        out_ptr    = (float*)d_out;
    }

    cudaFuncSetAttribute(rnn_rec_tf32,
                         cudaFuncAttributeMaxDynamicSharedMemorySize, RSM_BYTES);

    const int M = T_SEQ * NBATCH;  // 65536

    // phase 1: zi = x @ W_in^T
    {
        dim3 grid(DH / 128, M / 128);
        gemm_tf32_nt<false><<<grid, 256>>>(x, W_in, nullptr, zi_ptr, M, DH, DIN);
    }
    // phase 2: recurrence (8 clusters x 8 CTAs, 2 batch-groups per cluster)
    rnn_rec_tf32<<<NCLUS * 8, 256, RSM_BYTES>>>(U, V, b_h, zi_ptr, hidden_ptr, ppart);

    // phase 3: output = hidden @ W_out^T + b_out
    if (do_output) {
        dim3 grid(DOUT / 128, M / 128);
        gemm_tf32_nt<true><<<grid, 256>>>(hidden_ptr, W_out, b_out, out_ptr, M, DOUT, DH);
    }
}